// round 3
// baseline (speedup 1.0000x reference)
#include <cuda_runtime.h>
#include <math.h>

typedef unsigned long long u64;

#define TPB 256
#define PA 72      // pitch of sAT [32 d][rows]
#define PW 260     // pitch of sWT [32 d][cols<=256]

#define OUT_GATE_BASE 33554432UL   // B*M*D

// y scratch: [B,M,D] fp32 = 128MB
__device__ float g_y[32768u * 4u * 256u];

// ---------- packed fp32 helpers (Blackwell f32x2) ----------
static __device__ __forceinline__ u64 ffma2(u64 a, u64 b, u64 c) {
    u64 d;
    asm("fma.rn.f32x2 %0, %1, %2, %3;" : "=l"(d) : "l"(a), "l"(b), "l"(c));
    return d;
}
static __device__ __forceinline__ u64 dup2(float a) {
    u64 d;
    asm("mov.b64 %0, {%1, %1};" : "=l"(d) : "f"(a));
    return d;
}
static __device__ __forceinline__ float2 unpk(u64 p) {
    float2 r;
    asm("mov.b64 {%0, %1}, %2;" : "=f"(r.x), "=f"(r.y) : "l"(p));
    return r;
}

// ---------- tile staging ----------
// A[r][c0 + 0..31] -> sAT[d][r]   (A may be global or shared)
template<int R>
static __device__ __forceinline__ void ldA32(const float* __restrict__ A, int lda, int c0,
                                             float* sAT, int tid) {
    for (int idx = tid; idx < R * 8; idx += TPB) {
        const int r = idx >> 3, q = idx & 7;
        const float4 v = *reinterpret_cast<const float4*>(A + (size_t)r * lda + c0 + (q << 2));
        const int d = q << 2;
        sAT[(d + 0) * PA + r] = v.x;
        sAT[(d + 1) * PA + r] = v.y;
        sAT[(d + 2) * PA + r] = v.z;
        sAT[(d + 3) * PA + r] = v.w;
    }
}

// W[c][c0 + 0..31] -> sWT[d][c], c < ncols
static __device__ __forceinline__ void ldW32(const float* __restrict__ W, int ncols, int ldw,
                                             int c0, float* sWT, int tid) {
    for (int idx = tid; idx < ncols * 8; idx += TPB) {
        const int c = idx >> 3, q = idx & 7;
        const float4 v = *reinterpret_cast<const float4*>(W + (size_t)c * ldw + c0 + (q << 2));
        const int d = q << 2;
        sWT[(d + 0) * PW + c] = v.x;
        sWT[(d + 1) * PW + c] = v.y;
        sWT[(d + 2) * PW + c] = v.z;
        sWT[(d + 3) * PW + c] = v.w;
    }
}

// 8x8 tile mma over one 32-d tile: rowg=tid>>5 (8 rows), colg=tid&31 (8 cols)
static __device__ __forceinline__ void mma8x8(const float* sAT, const float* sWT,
                                              u64 acc[8][4], int rowg, int colg) {
#pragma unroll 8
    for (int d = 0; d < 32; ++d) {
        const float* ap = sAT + d * PA + (rowg << 3);
        const float4 a0 = *reinterpret_cast<const float4*>(ap);
        const float4 a1 = *reinterpret_cast<const float4*>(ap + 4);
        const ulonglong2 w0 = *reinterpret_cast<const ulonglong2*>(sWT + d * PW + (colg << 3));
        const ulonglong2 w1 = *reinterpret_cast<const ulonglong2*>(sWT + d * PW + (colg << 3) + 4);
        const float a[8] = {a0.x, a0.y, a0.z, a0.w, a1.x, a1.y, a1.z, a1.w};
#pragma unroll
        for (int i = 0; i < 8; ++i) {
            const u64 ad = dup2(a[i]);
            acc[i][0] = ffma2(ad, w0.x, acc[i][0]);
            acc[i][1] = ffma2(ad, w0.y, acc[i][1]);
            acc[i][2] = ffma2(ad, w1.x, acc[i][2]);
            acc[i][3] = ffma2(ad, w1.y, acc[i][3]);
        }
    }
}

// 4x4 tile mma (16-row GEMMs): rowg4=tid>>6 (4 rows), cg=tid&63 (4 cols)
static __device__ __forceinline__ void mma4x4(const float* sAT, const float* sWT,
                                              u64 acc[4][2], int rowg4, int cg) {
#pragma unroll 8
    for (int d = 0; d < 32; ++d) {
        const float4 a4 = *reinterpret_cast<const float4*>(sAT + d * PA + (rowg4 << 2));
        const ulonglong2 w = *reinterpret_cast<const ulonglong2*>(sWT + d * PW + (cg << 2));
        const float a[4] = {a4.x, a4.y, a4.z, a4.w};
#pragma unroll
        for (int i = 0; i < 4; ++i) {
            const u64 ad = dup2(a[i]);
            acc[i][0] = ffma2(ad, w.x, acc[i][0]);
            acc[i][1] = ffma2(ad, w.y, acc[i][1]);
        }
    }
}

// =====================================================================
// Kernel 1: KV proj + attention + Wo + gate + LayerNorm -> g_y, gate->out
// grid (2048, 4), 16 batch elements per block
// =====================================================================
#define SM1_AT   0
#define SM1_WT   2304
#define SM1_K    10624
#define SM1_V    27008
#define SM1_Q    43392
#define SM1_AO   47488
#define SM1_GH   51584
#define SM1_GATE 52608
#define SM1_FLOATS (52624)
#define SM1_BYTES  (SM1_FLOATS * 4)

__global__ __launch_bounds__(TPB, 1)
void gcma_part1(const float* __restrict__ x,
                const float* __restrict__ Wq, const float* __restrict__ bq,
                const float* __restrict__ Wk, const float* __restrict__ bk,
                const float* __restrict__ Wv, const float* __restrict__ bv,
                const float* __restrict__ Wo, const float* __restrict__ bo,
                const float* __restrict__ g1w, const float* __restrict__ g1b,
                const float* __restrict__ g2w, const float* __restrict__ g2b,
                const float* __restrict__ lng, const float* __restrict__ lnb,
                float* __restrict__ out)
{
    extern __shared__ float sm[];
    float* sAT   = sm + SM1_AT;
    float* sWT   = sm + SM1_WT;
    float* sK    = sm + SM1_K;
    float* sV    = sm + SM1_V;
    float* sQ    = sm + SM1_Q;
    float* sAO   = sm + SM1_AO;
    float* sGH   = sm + SM1_GH;
    float* sGate = sm + SM1_GATE;

    const int tid = threadIdx.x;
    const int m   = blockIdx.y;
    const int b0  = blockIdx.x * 16;
    const long g0 = (long)b0 * 4;

    const int rowg  = tid >> 5;   // 0..7
    const int colg  = tid & 31;   // 0..31
    const int rowg4 = tid >> 6;   // 0..3
    const int cg    = tid & 63;   // 0..63

    const float* Xblk = x + (size_t)g0 * 256;

    // ---- K and V: [64 x 256] ----
    for (int kv = 0; kv < 2; ++kv) {
        const float* W    = (kv ? Wv : Wk) + (size_t)m * 65536;
        const float* bias = (kv ? bv : bk) + m * 256;
        float* sOut = kv ? sV : sK;
        u64 acc[8][4];
#pragma unroll
        for (int i = 0; i < 8; ++i)
#pragma unroll
            for (int j = 0; j < 4; ++j) acc[i][j] = 0ULL;
        for (int dt = 0; dt < 8; ++dt) {
            __syncthreads();
            ldA32<64>(Xblk, 256, dt * 32, sAT, tid);
            ldW32(W, 256, 256, dt * 32, sWT, tid);
            __syncthreads();
            mma8x8(sAT, sWT, acc, rowg, colg);
        }
        float bl[8];
#pragma unroll
        for (int j = 0; j < 8; ++j) bl[j] = bias[colg * 8 + j];
#pragma unroll
        for (int i = 0; i < 8; ++i) {
            const int r = rowg * 8 + i;
            const float2 p0 = unpk(acc[i][0]), p1 = unpk(acc[i][1]);
            const float2 p2 = unpk(acc[i][2]), p3 = unpk(acc[i][3]);
            float4 o0 = make_float4(p0.x + bl[0], p0.y + bl[1], p1.x + bl[2], p1.y + bl[3]);
            float4 o1 = make_float4(p2.x + bl[4], p2.y + bl[5], p3.x + bl[6], p3.y + bl[7]);
            *reinterpret_cast<float4*>(sOut + r * 256 + colg * 8)     = o0;
            *reinterpret_cast<float4*>(sOut + r * 256 + colg * 8 + 4) = o1;
        }
    }

    // ---- Q: [16 x 256], scaled ----
    {
        const float* W    = Wq + (size_t)m * 65536;
        const float* bias = bq + m * 256;
        const float* A    = x + (size_t)(g0 + m) * 256;   // stride 1024
        u64 acc[4][2];
#pragma unroll
        for (int i = 0; i < 4; ++i) { acc[i][0] = 0ULL; acc[i][1] = 0ULL; }
        for (int dt = 0; dt < 8; ++dt) {
            __syncthreads();
            ldA32<16>(A, 1024, dt * 32, sAT, tid);
            ldW32(W, 256, 256, dt * 32, sWT, tid);
            __syncthreads();
            mma4x4(sAT, sWT, acc, rowg4, cg);
        }
        const float b0c = bias[cg * 4], b1c = bias[cg * 4 + 1];
        const float b2c = bias[cg * 4 + 2], b3c = bias[cg * 4 + 3];
#pragma unroll
        for (int i = 0; i < 4; ++i) {
            const int r = rowg4 * 4 + i;
            const float2 p0 = unpk(acc[i][0]), p1 = unpk(acc[i][1]);
            float4 o = make_float4((p0.x + b0c) * 0.17677669529663687f,
                                   (p0.y + b1c) * 0.17677669529663687f,
                                   (p1.x + b2c) * 0.17677669529663687f,
                                   (p1.y + b3c) * 0.17677669529663687f);
            *reinterpret_cast<float4*>(sQ + r * 256 + cg * 4) = o;
        }
    }
    __syncthreads();

    // ---- attention (seq 4), Oh overwrites sQ ----
    if (tid < 128) {
        const int bl = tid >> 3, h = tid & 7;
        const float* qp = sQ + bl * 256 + h * 32;
        float q[32];
#pragma unroll
        for (int i = 0; i < 32; ++i) q[i] = qp[i];
        float s[4];
#pragma unroll
        for (int n = 0; n < 4; ++n) {
            const float* kp = sK + (bl * 4 + n) * 256 + h * 32;
            float dot = 0.f;
#pragma unroll
            for (int i = 0; i < 32; ++i) dot = fmaf(q[i], kp[i], dot);
            s[n] = dot;
        }
        const float mx = fmaxf(fmaxf(s[0], s[1]), fmaxf(s[2], s[3]));
        float e[4], se = 0.f;
#pragma unroll
        for (int n = 0; n < 4; ++n) { e[n] = expf(s[n] - mx); se += e[n]; }
        const float inv = 1.f / se;
        float o[32];
#pragma unroll
        for (int i = 0; i < 32; ++i) o[i] = 0.f;
#pragma unroll
        for (int n = 0; n < 4; ++n) {
            const float p = e[n] * inv;
            const float* vp = sV + (bl * 4 + n) * 256 + h * 32;
#pragma unroll
            for (int i = 0; i < 32; ++i) o[i] = fmaf(p, vp[i], o[i]);
        }
        float* op = sQ + bl * 256 + h * 32;
#pragma unroll
        for (int i = 0; i < 32; ++i) op[i] = o[i];
    }
    __syncthreads();

    // ---- Wo: attn_out [16 x 256] -> sAO ----
    {
        const float* W    = Wo + (size_t)m * 65536;
        const float* bias = bo + m * 256;
        u64 acc[4][2];
#pragma unroll
        for (int i = 0; i < 4; ++i) { acc[i][0] = 0ULL; acc[i][1] = 0ULL; }
        for (int dt = 0; dt < 8; ++dt) {
            __syncthreads();
            ldA32<16>(sQ, 256, dt * 32, sAT, tid);
            ldW32(W, 256, 256, dt * 32, sWT, tid);
            __syncthreads();
            mma4x4(sAT, sWT, acc, rowg4, cg);
        }
        const float b0c = bias[cg * 4], b1c = bias[cg * 4 + 1];
        const float b2c = bias[cg * 4 + 2], b3c = bias[cg * 4 + 3];
#pragma unroll
        for (int i = 0; i < 4; ++i) {
            const int r = rowg4 * 4 + i;
            const float2 p0 = unpk(acc[i][0]), p1 = unpk(acc[i][1]);
            float4 o = make_float4(p0.x + b0c, p0.y + b1c, p1.x + b2c, p1.y + b3c);
            *reinterpret_cast<float4*>(sAO + r * 256 + cg * 4) = o;
        }
    }

    // ---- gate layer 1: [16 x 64] ----
    {
        const float* W = g1w + (size_t)m * 32768;   // [64][512]
        float gacc[4] = {0.f, 0.f, 0.f, 0.f};
        for (int dt = 0; dt < 16; ++dt) {
            __syncthreads();
            if (dt < 8) ldA32<16>(x + (size_t)(g0 + m) * 256, 1024, dt * 32, sAT, tid);
            else        ldA32<16>(sAO, 256, (dt - 8) * 32, sAT, tid);
            ldW32(W, 64, 512, dt * 32, sWT, tid);
            __syncthreads();
#pragma unroll 8
            for (int d = 0; d < 32; ++d) {
                const float4 a4 = *reinterpret_cast<const float4*>(sAT + d * PA + (rowg4 << 2));
                const float w = sWT[d * PW + cg];
                gacc[0] = fmaf(a4.x, w, gacc[0]);
                gacc[1] = fmaf(a4.y, w, gacc[1]);
                gacc[2] = fmaf(a4.z, w, gacc[2]);
                gacc[3] = fmaf(a4.w, w, gacc[3]);
            }
        }
        const float gb = g1b[m * 64 + cg];
#pragma unroll
        for (int i = 0; i < 4; ++i)
            sGH[(rowg4 * 4 + i) * 64 + cg] = tanhf(gacc[i] + gb);
    }
    __syncthreads();

    // ---- gate layer 2 + sigmoid ----
    if (tid < 16) {
        const float* g2 = g2w + m * 64;
        float dot = g2b[m];
#pragma unroll 8
        for (int j = 0; j < 64; ++j) dot = fmaf(sGH[tid * 64 + j], g2[j], dot);
        const float gate = 1.f / (1.f + expf(-dot));
        sGate[tid] = gate;
        out[OUT_GATE_BASE + (size_t)(b0 + tid) * 4 + m] = gate;
    }
    __syncthreads();

    // ---- residual + LayerNorm -> g_y ----
    {
        const int w = tid >> 5, lane = tid & 31;
        for (int bl = w; bl < 16; bl += 8) {
            const float* xr = x + (size_t)(g0 + bl * 4 + m) * 256;
            const float gate = sGate[bl];
            float r[8];
            float sum = 0.f;
#pragma unroll
            for (int k = 0; k < 8; ++k) {
                const int d = k * 32 + lane;
                r[k] = xr[d] + gate * sAO[bl * 256 + d];
                sum += r[k];
            }
#pragma unroll
            for (int o = 16; o; o >>= 1) sum += __shfl_xor_sync(0xffffffffu, sum, o);
            const float mu = sum * (1.f / 256.f);
            float var = 0.f;
#pragma unroll
            for (int k = 0; k < 8; ++k) { const float t = r[k] - mu; var = fmaf(t, t, var); }
#pragma unroll
            for (int o = 16; o; o >>= 1) var += __shfl_xor_sync(0xffffffffu, var, o);
            const float rs = rsqrtf(var * (1.f / 256.f) + 1e-5f);
            float* yr = g_y + (size_t)(g0 + bl * 4 + m) * 256;
#pragma unroll
            for (int k = 0; k < 8; ++k) {
                const int d = k * 32 + lane;
                yr[d] = (r[k] - mu) * rs * lng[m * 256 + d] + lnb[m * 256 + d];
            }
        }
    }
}

// =====================================================================
// Kernel 2: FF over y: out = y + f2( gelu(f1(y)) )
// grid (512, 4), 64 batch rows per block, hf chunked by 256
// =====================================================================
#define SM2_Y   0
#define SM2_HF  16640
#define SM2_AT  33280
#define SM2_WT  35584
#define SM2_FLOATS 43904
#define SM2_BYTES  (SM2_FLOATS * 4)
#define PY 260

__global__ __launch_bounds__(TPB, 1)
void gcma_part2(const float* __restrict__ f1w, const float* __restrict__ f1b,
                const float* __restrict__ f2w, const float* __restrict__ f2b,
                float* __restrict__ out)
{
    extern __shared__ float sm[];
    float* sY  = sm + SM2_Y;    // [64][260]
    float* sHF = sm + SM2_HF;   // [64][260]
    float* sAT = sm + SM2_AT;
    float* sWT = sm + SM2_WT;

    const int tid = threadIdx.x;
    const int m   = blockIdx.y;
    const int b0  = blockIdx.x * 64;

    const int rowg = tid >> 5;   // 0..7 (8 rows each)
    const int colg = tid & 31;   // 0..31 (8 cols each)

    // load y tile [64 rows][256]
    for (int idx = tid; idx < 4096; idx += TPB) {
        const int r = idx >> 6, q = idx & 63;
        const float4 v = *reinterpret_cast<const float4*>(
            g_y + ((size_t)(b0 + r) * 4 + m) * 256 + q * 4);
        *reinterpret_cast<float4*>(sY + r * PY + q * 4) = v;
    }

    u64 facc[8][4];
#pragma unroll
    for (int i = 0; i < 8; ++i)
#pragma unroll
        for (int j = 0; j < 4; ++j) facc[i][j] = 0ULL;

    for (int ch = 0; ch < 4; ++ch) {
        // ---- FF1 chunk: hf[:, ch*256 .. +255] ----
        u64 hacc[8][4];
#pragma unroll
        for (int i = 0; i < 8; ++i)
#pragma unroll
            for (int j = 0; j < 4; ++j) hacc[i][j] = 0ULL;
        const float* W1 = f1w + (size_t)m * 262144 + (size_t)ch * 65536; // rows=outcols, ld 256
        for (int dt = 0; dt < 8; ++dt) {
            __syncthreads();
            ldA32<64>(sY, PY, dt * 32, sAT, tid);
            ldW32(W1, 256, 256, dt * 32, sWT, tid);
            __syncthreads();
            mma8x8(sAT, sWT, hacc, rowg, colg);
        }
        // bias + exact GELU, store row-major into sHF
        {
            const float* b1 = f1b + m * 1024 + ch * 256 + colg * 8;
            float bl[8];
#pragma unroll
            for (int j = 0; j < 8; ++j) bl[j] = b1[j];
#pragma unroll
            for (int i = 0; i < 8; ++i) {
                const int r = rowg * 8 + i;
                const float2 p0 = unpk(hacc[i][0]), p1 = unpk(hacc[i][1]);
                const float2 p2 = unpk(hacc[i][2]), p3 = unpk(hacc[i][3]);
                float v[8] = {p0.x + bl[0], p0.y + bl[1], p1.x + bl[2], p1.y + bl[3],
                              p2.x + bl[4], p2.y + bl[5], p3.x + bl[6], p3.y + bl[7]};
#pragma unroll
                for (int j = 0; j < 8; ++j)
                    v[j] = 0.5f * v[j] * (1.f + erff(v[j] * 0.7071067811865476f));
                *reinterpret_cast<float4*>(sHF + r * PY + colg * 8)     = make_float4(v[0], v[1], v[2], v[3]);
                *reinterpret_cast<float4*>(sHF + r * PY + colg * 8 + 4) = make_float4(v[4], v[5], v[6], v[7]);
            }
        }
        // ---- FF2 partial: facc += hf_chunk @ f2w[:, ch*256..]^T ----
        const float* W2 = f2w + (size_t)m * 262144;  // rows=256 outcols, ld 1024
        for (int dt = 0; dt < 8; ++dt) {
            __syncthreads();
            ldA32<64>(sHF, PY, dt * 32, sAT, tid);
            ldW32(W2, 256, 1024, ch * 256 + dt * 32, sWT, tid);
            __syncthreads();
            mma8x8(sAT, sWT, facc, rowg, colg);
        }
    }

    // ---- epilogue: out = y + ff + f2b ----
    {
        float bl[8];
        const float* b2 = f2b + m * 256 + colg * 8;
#pragma unroll
        for (int j = 0; j < 8; ++j) bl[j] = b2[j];
#pragma unroll
        for (int i = 0; i < 8; ++i) {
            const int r = rowg * 8 + i;
            const float4 y0 = *reinterpret_cast<const float4*>(sY + r * PY + colg * 8);
            const float4 y1 = *reinterpret_cast<const float4*>(sY + r * PY + colg * 8 + 4);
            const float2 p0 = unpk(facc[i][0]), p1 = unpk(facc[i][1]);
            const float2 p2 = unpk(facc[i][2]), p3 = unpk(facc[i][3]);
            float4 o0 = make_float4(y0.x + p0.x + bl[0], y0.y + p0.y + bl[1],
                                    y0.z + p1.x + bl[2], y0.w + p1.y + bl[3]);
            float4 o1 = make_float4(y1.x + p2.x + bl[4], y1.y + p2.y + bl[5],
                                    y1.z + p3.x + bl[6], y1.w + p3.y + bl[7]);
            float* op = out + ((size_t)(b0 + r) * 4 + m) * 256 + colg * 8;
            *reinterpret_cast<float4*>(op)     = o0;
            *reinterpret_cast<float4*>(op + 4) = o1;
        }
    }
}

extern "C" void kernel_launch(void* const* d_in, const int* in_sizes, int n_in,
                              void* d_out, int out_size) {
    const float* x   = (const float*)d_in[0];
    const float* Wq  = (const float*)d_in[1];
    const float* bq  = (const float*)d_in[2];
    const float* Wk  = (const float*)d_in[3];
    const float* bk  = (const float*)d_in[4];
    const float* Wv  = (const float*)d_in[5];
    const float* bv  = (const float*)d_in[6];
    const float* Wo  = (const float*)d_in[7];
    const float* bo  = (const float*)d_in[8];
    const float* g1w = (const float*)d_in[9];
    const float* g1b = (const float*)d_in[10];
    const float* g2w = (const float*)d_in[11];
    const float* g2b = (const float*)d_in[12];
    const float* lng = (const float*)d_in[13];
    const float* lnb = (const float*)d_in[14];
    const float* f1w = (const float*)d_in[15];
    const float* f1b = (const float*)d_in[16];
    const float* f2w = (const float*)d_in[17];
    const float* f2b = (const float*)d_in[18];
    float* out = (float*)d_out;

    cudaFuncSetAttribute(gcma_part1, cudaFuncAttributeMaxDynamicSharedMemorySize, SM1_BYTES);
    cudaFuncSetAttribute(gcma_part2, cudaFuncAttributeMaxDynamicSharedMemorySize, SM2_BYTES);

    dim3 grid1(32768 / 16, 4, 1);
    gcma_part1<<<grid1, TPB, SM1_BYTES>>>(x, Wq, bq, Wk, bk, Wv, bv, Wo, bo,
                                          g1w, g1b, g2w, g2b, lng, lnb, out);
    dim3 grid2(32768 / 64, 4, 1);
    gcma_part2<<<grid2, TPB, SM2_BYTES>>>(f1w, f1b, f2w, f2b, out);
}

// round 4
// speedup vs baseline: 1.1399x; 1.1399x over previous
#include <cuda_runtime.h>
#include <math.h>

typedef unsigned long long u64;

#define TPB 256
#define PW 260     // pitch of transposed W tile [32 d][cols<=256]

#define OUT_GATE_BASE 33554432UL   // B*M*D

// y scratch: [B,M,D] fp32 = 128MB
__device__ float g_y[32768u * 4u * 256u];

// ---------- packed fp32 helpers (Blackwell f32x2) ----------
static __device__ __forceinline__ u64 ffma2(u64 a, u64 b, u64 c) {
    u64 d;
    asm("fma.rn.f32x2 %0, %1, %2, %3;" : "=l"(d) : "l"(a), "l"(b), "l"(c));
    return d;
}
static __device__ __forceinline__ u64 dup2(float a) {
    u64 d;
    asm("mov.b64 %0, {%1, %1};" : "=l"(d) : "f"(a));
    return d;
}
static __device__ __forceinline__ float2 unpk(u64 p) {
    float2 r;
    asm("mov.b64 {%0, %1}, %2;" : "=f"(r.x), "=f"(r.y) : "l"(p));
    return r;
}
static __device__ __forceinline__ float comp4(const float4& v, int dd) {
    return dd == 0 ? v.x : dd == 1 ? v.y : dd == 2 ? v.z : v.w;
}

// ---------- W tile staging: W[c][c0 + 0..31] -> sWT[d][c], transposed ----------
static __device__ __forceinline__ void ldW32(const float* __restrict__ W, int ncols, int ldw,
                                             int c0, float* sWT, int tid) {
    for (int idx = tid; idx < ncols * 8; idx += TPB) {
        const int c = idx >> 3, q = idx & 7;
        const float4 v = *reinterpret_cast<const float4*>(W + (size_t)c * ldw + c0 + (q << 2));
        const int d = q << 2;
        sWT[(d + 0) * PW + c] = v.x;
        sWT[(d + 1) * PW + c] = v.y;
        sWT[(d + 2) * PW + c] = v.z;
        sWT[(d + 3) * PW + c] = v.w;
    }
}

// ---------- mma: 64-row GEMM, A row-major smem (broadcast reads) ----------
// aRow = sA + rowg*8*lda + c0 ; acc[8][4] packed pairs ; colg = tid&31
static __device__ __forceinline__ void mma64b(const float* __restrict__ aRow, int lda,
                                              const float* __restrict__ sWT,
                                              u64 acc[8][4], int colg) {
#pragma unroll
    for (int d4 = 0; d4 < 8; ++d4) {
        float4 a4[8];
#pragma unroll
        for (int i = 0; i < 8; ++i)
            a4[i] = *reinterpret_cast<const float4*>(aRow + i * lda + (d4 << 2));
#pragma unroll
        for (int dd = 0; dd < 4; ++dd) {
            const int d = (d4 << 2) + dd;
            const ulonglong2 w0 = *reinterpret_cast<const ulonglong2*>(sWT + d * PW + (colg << 3));
            const ulonglong2 w1 = *reinterpret_cast<const ulonglong2*>(sWT + d * PW + (colg << 3) + 4);
#pragma unroll
            for (int i = 0; i < 8; ++i) {
                const u64 ad = dup2(comp4(a4[i], dd));
                acc[i][0] = ffma2(ad, w0.x, acc[i][0]);
                acc[i][1] = ffma2(ad, w0.y, acc[i][1]);
                acc[i][2] = ffma2(ad, w1.x, acc[i][2]);
                acc[i][3] = ffma2(ad, w1.y, acc[i][3]);
            }
        }
    }
}

// ---------- mma: 16-row GEMM, A row-major smem (broadcast) ----------
// aRow = sA + rowg4*4*lda + c0 ; acc[4][2] ; cg = tid&63 (4 cols each)
static __device__ __forceinline__ void mma16b(const float* __restrict__ aRow, int lda,
                                              const float* __restrict__ sWT,
                                              u64 acc[4][2], int cg) {
#pragma unroll
    for (int d4 = 0; d4 < 8; ++d4) {
        float4 a4[4];
#pragma unroll
        for (int i = 0; i < 4; ++i)
            a4[i] = *reinterpret_cast<const float4*>(aRow + i * lda + (d4 << 2));
#pragma unroll
        for (int dd = 0; dd < 4; ++dd) {
            const int d = (d4 << 2) + dd;
            const ulonglong2 w = *reinterpret_cast<const ulonglong2*>(sWT + d * PW + (cg << 2));
#pragma unroll
            for (int i = 0; i < 4; ++i) {
                const u64 ad = dup2(comp4(a4[i], dd));
                acc[i][0] = ffma2(ad, w.x, acc[i][0]);
                acc[i][1] = ffma2(ad, w.y, acc[i][1]);
            }
        }
    }
}

// ---------- mma: 16-row x 64-col (gate1), 1 col/thread ----------
static __device__ __forceinline__ void mmagb(const float* __restrict__ aRow, int lda,
                                             const float* __restrict__ sWT,
                                             float gacc[4], int cg) {
#pragma unroll
    for (int d4 = 0; d4 < 8; ++d4) {
        float4 a4[4];
#pragma unroll
        for (int i = 0; i < 4; ++i)
            a4[i] = *reinterpret_cast<const float4*>(aRow + i * lda + (d4 << 2));
#pragma unroll
        for (int dd = 0; dd < 4; ++dd) {
            const int d = (d4 << 2) + dd;
            const float w = sWT[d * PW + cg];
#pragma unroll
            for (int i = 0; i < 4; ++i)
                gacc[i] = fmaf(comp4(a4[i], dd), w, gacc[i]);
        }
    }
}

// =====================================================================
// Kernel 1: KV proj + attention + Wo + gate + LayerNorm -> g_y, gate->out
// grid (2048, 4), 16 batch elements per block
// =====================================================================
#define SM1_X    0        // [64][256]
#define SM1_WT   16384    // [32][260]
#define SM1_Q    24704    // [16][256]  (Q, then Oh)
#define SM1_KV   28800    // [64][256]  (K, then V)
#define SM1_P    45184    // [16][8][4] probs
#define SM1_AO   45696    // [16][256]
#define SM1_GH   49792    // [16][64]
#define SM1_GATE 50816    // [16]
#define SM1_FLOATS 50832
#define SM1_BYTES  (SM1_FLOATS * 4)

__global__ __launch_bounds__(TPB, 1)
void gcma_part1(const float* __restrict__ x,
                const float* __restrict__ Wq, const float* __restrict__ bq,
                const float* __restrict__ Wk, const float* __restrict__ bk,
                const float* __restrict__ Wv, const float* __restrict__ bv,
                const float* __restrict__ Wo, const float* __restrict__ bo,
                const float* __restrict__ g1w, const float* __restrict__ g1b,
                const float* __restrict__ g2w, const float* __restrict__ g2b,
                const float* __restrict__ lng, const float* __restrict__ lnb,
                float* __restrict__ out)
{
    extern __shared__ float sm[];
    float* sX    = sm + SM1_X;
    float* sWT   = sm + SM1_WT;
    float* sQ    = sm + SM1_Q;
    float* sKV   = sm + SM1_KV;
    float* sP    = sm + SM1_P;
    float* sAO   = sm + SM1_AO;
    float* sGH   = sm + SM1_GH;
    float* sGate = sm + SM1_GATE;

    const int tid = threadIdx.x;
    const int m   = blockIdx.y;
    const int b0  = blockIdx.x * 16;
    const long g0 = (long)b0 * 4;

    const int rowg  = tid >> 5;   // 0..7  (warp id)
    const int colg  = tid & 31;
    const int rowg4 = tid >> 6;   // 0..3
    const int cg    = tid & 63;

    // ---- stage X block [64 rows][256] row-major ----
    {
        const float* Xblk = x + (size_t)g0 * 256;
        for (int idx = tid; idx < 4096; idx += TPB) {
            const int r = idx >> 6, q = idx & 63;
            *reinterpret_cast<float4*>(sX + r * 256 + q * 4) =
                *reinterpret_cast<const float4*>(Xblk + r * 256 + q * 4);
        }
    }

    // ---- Q: [16 x 256], scaled ----
    {
        const float* W    = Wq + (size_t)m * 65536;
        const float* bias = bq + m * 256;
        u64 acc[4][2];
#pragma unroll
        for (int i = 0; i < 4; ++i) { acc[i][0] = 0ULL; acc[i][1] = 0ULL; }
        for (int dt = 0; dt < 8; ++dt) {
            __syncthreads();
            ldW32(W, 256, 256, dt * 32, sWT, tid);
            __syncthreads();
            mma16b(sX + m * 256 + rowg4 * 4 * 1024 + dt * 32, 1024, sWT, acc, cg);
        }
        const float bc0 = bias[cg * 4], bc1 = bias[cg * 4 + 1];
        const float bc2 = bias[cg * 4 + 2], bc3 = bias[cg * 4 + 3];
#pragma unroll
        for (int i = 0; i < 4; ++i) {
            const int r = rowg4 * 4 + i;
            const float2 p0 = unpk(acc[i][0]), p1 = unpk(acc[i][1]);
            *reinterpret_cast<float4*>(sQ + r * 256 + cg * 4) =
                make_float4((p0.x + bc0) * 0.17677669529663687f,
                            (p0.y + bc1) * 0.17677669529663687f,
                            (p1.x + bc2) * 0.17677669529663687f,
                            (p1.y + bc3) * 0.17677669529663687f);
        }
    }

    // ---- K: [64 x 256] -> sKV ----
    {
        const float* W    = Wk + (size_t)m * 65536;
        const float* bias = bk + m * 256;
        u64 acc[8][4];
#pragma unroll
        for (int i = 0; i < 8; ++i)
#pragma unroll
            for (int j = 0; j < 4; ++j) acc[i][j] = 0ULL;
        for (int dt = 0; dt < 8; ++dt) {
            __syncthreads();
            ldW32(W, 256, 256, dt * 32, sWT, tid);
            __syncthreads();
            mma64b(sX + rowg * 8 * 256 + dt * 32, 256, sWT, acc, colg);
        }
        float bl[8];
#pragma unroll
        for (int j = 0; j < 8; ++j) bl[j] = bias[colg * 8 + j];
#pragma unroll
        for (int i = 0; i < 8; ++i) {
            const int r = rowg * 8 + i;
            const float2 p0 = unpk(acc[i][0]), p1 = unpk(acc[i][1]);
            const float2 p2 = unpk(acc[i][2]), p3 = unpk(acc[i][3]);
            *reinterpret_cast<float4*>(sKV + r * 256 + colg * 8) =
                make_float4(p0.x + bl[0], p0.y + bl[1], p1.x + bl[2], p1.y + bl[3]);
            *reinterpret_cast<float4*>(sKV + r * 256 + colg * 8 + 4) =
                make_float4(p2.x + bl[4], p2.y + bl[5], p3.x + bl[6], p3.y + bl[7]);
        }
    }
    __syncthreads();

    // ---- scores + softmax -> probs sP ----
    if (tid < 128) {
        const int bl = tid >> 3, h = tid & 7;
        const float* qp = sQ + bl * 256 + h * 32;
        float q[32];
#pragma unroll
        for (int i = 0; i < 32; ++i) q[i] = qp[i];
        float s[4];
#pragma unroll
        for (int n = 0; n < 4; ++n) {
            const float* kp = sKV + (bl * 4 + n) * 256 + h * 32;
            float dot = 0.f;
#pragma unroll
            for (int i = 0; i < 32; ++i) dot = fmaf(q[i], kp[i], dot);
            s[n] = dot;
        }
        const float mx = fmaxf(fmaxf(s[0], s[1]), fmaxf(s[2], s[3]));
        float e[4], se = 0.f;
#pragma unroll
        for (int n = 0; n < 4; ++n) { e[n] = expf(s[n] - mx); se += e[n]; }
        const float inv = 1.f / se;
#pragma unroll
        for (int n = 0; n < 4; ++n) sP[tid * 4 + n] = e[n] * inv;
    }

    // ---- V: [64 x 256] -> sKV (overwrites K; ordered by dt-loop barriers) ----
    {
        const float* W    = Wv + (size_t)m * 65536;
        const float* bias = bv + m * 256;
        u64 acc[8][4];
#pragma unroll
        for (int i = 0; i < 8; ++i)
#pragma unroll
            for (int j = 0; j < 4; ++j) acc[i][j] = 0ULL;
        for (int dt = 0; dt < 8; ++dt) {
            __syncthreads();
            ldW32(W, 256, 256, dt * 32, sWT, tid);
            __syncthreads();
            mma64b(sX + rowg * 8 * 256 + dt * 32, 256, sWT, acc, colg);
        }
        float bl[8];
#pragma unroll
        for (int j = 0; j < 8; ++j) bl[j] = bias[colg * 8 + j];
#pragma unroll
        for (int i = 0; i < 8; ++i) {
            const int r = rowg * 8 + i;
            const float2 p0 = unpk(acc[i][0]), p1 = unpk(acc[i][1]);
            const float2 p2 = unpk(acc[i][2]), p3 = unpk(acc[i][3]);
            *reinterpret_cast<float4*>(sKV + r * 256 + colg * 8) =
                make_float4(p0.x + bl[0], p0.y + bl[1], p1.x + bl[2], p1.y + bl[3]);
            *reinterpret_cast<float4*>(sKV + r * 256 + colg * 8 + 4) =
                make_float4(p2.x + bl[4], p2.y + bl[5], p3.x + bl[6], p3.y + bl[7]);
        }
    }
    __syncthreads();

    // ---- Oh = P @ V -> sQ (overwrites Q) ----
    if (tid < 128) {
        const int bl = tid >> 3, h = tid & 7;
        float o[32];
#pragma unroll
        for (int i = 0; i < 32; ++i) o[i] = 0.f;
#pragma unroll
        for (int n = 0; n < 4; ++n) {
            const float p = sP[tid * 4 + n];
            const float* vp = sKV + (bl * 4 + n) * 256 + h * 32;
#pragma unroll
            for (int i = 0; i < 32; ++i) o[i] = fmaf(p, vp[i], o[i]);
        }
        float* op = sQ + bl * 256 + h * 32;
#pragma unroll
        for (int i = 0; i < 32; ++i) op[i] = o[i];
    }

    // ---- Wo: attn_out [16 x 256] -> sAO ----
    {
        const float* W    = Wo + (size_t)m * 65536;
        const float* bias = bo + m * 256;
        u64 acc[4][2];
#pragma unroll
        for (int i = 0; i < 4; ++i) { acc[i][0] = 0ULL; acc[i][1] = 0ULL; }
        for (int dt = 0; dt < 8; ++dt) {
            __syncthreads();
            ldW32(W, 256, 256, dt * 32, sWT, tid);
            __syncthreads();
            mma16b(sQ + rowg4 * 4 * 256 + dt * 32, 256, sWT, acc, cg);
        }
        const float bc0 = bias[cg * 4], bc1 = bias[cg * 4 + 1];
        const float bc2 = bias[cg * 4 + 2], bc3 = bias[cg * 4 + 3];
#pragma unroll
        for (int i = 0; i < 4; ++i) {
            const int r = rowg4 * 4 + i;
            const float2 p0 = unpk(acc[i][0]), p1 = unpk(acc[i][1]);
            *reinterpret_cast<float4*>(sAO + r * 256 + cg * 4) =
                make_float4(p0.x + bc0, p0.y + bc1, p1.x + bc2, p1.y + bc3);
        }
    }

    // ---- gate layer 1: tanh([x_m ; AO] @ g1w^T) [16 x 64] ----
    {
        const float* W = g1w + (size_t)m * 32768;   // [64][512]
        float gacc[4] = {0.f, 0.f, 0.f, 0.f};
        for (int dt = 0; dt < 16; ++dt) {
            __syncthreads();
            ldW32(W, 64, 512, dt * 32, sWT, tid);
            __syncthreads();
            if (dt < 8)
                mmagb(sX + m * 256 + rowg4 * 4 * 1024 + dt * 32, 1024, sWT, gacc, cg);
            else
                mmagb(sAO + rowg4 * 4 * 256 + (dt - 8) * 32, 256, sWT, gacc, cg);
        }
        const float gb = g1b[m * 64 + cg];
#pragma unroll
        for (int i = 0; i < 4; ++i)
            sGH[(rowg4 * 4 + i) * 64 + cg] = tanhf(gacc[i] + gb);
    }
    __syncthreads();

    // ---- gate layer 2 + sigmoid ----
    if (tid < 16) {
        const float* g2 = g2w + m * 64;
        float dot = g2b[m];
#pragma unroll 8
        for (int j = 0; j < 64; ++j) dot = fmaf(sGH[tid * 64 + j], g2[j], dot);
        const float gate = 1.f / (1.f + expf(-dot));
        sGate[tid] = gate;
        out[OUT_GATE_BASE + (size_t)(b0 + tid) * 4 + m] = gate;
    }
    __syncthreads();

    // ---- residual + LayerNorm -> g_y ----
    {
        const int w = tid >> 5, lane = tid & 31;
        for (int bl = w; bl < 16; bl += 8) {
            const float* xr = sX + (bl * 4 + m) * 256;
            const float gate = sGate[bl];
            float r[8];
            float sum = 0.f;
#pragma unroll
            for (int k = 0; k < 8; ++k) {
                const int d = k * 32 + lane;
                r[k] = xr[d] + gate * sAO[bl * 256 + d];
                sum += r[k];
            }
#pragma unroll
            for (int o = 16; o; o >>= 1) sum += __shfl_xor_sync(0xffffffffu, sum, o);
            const float mu = sum * (1.f / 256.f);
            float var = 0.f;
#pragma unroll
            for (int k = 0; k < 8; ++k) { const float t = r[k] - mu; var = fmaf(t, t, var); }
#pragma unroll
            for (int o = 16; o; o >>= 1) var += __shfl_xor_sync(0xffffffffu, var, o);
            const float rs = rsqrtf(var * (1.f / 256.f) + 1e-5f);
            float* yr = g_y + (size_t)(g0 + bl * 4 + m) * 256;
#pragma unroll
            for (int k = 0; k < 8; ++k) {
                const int d = k * 32 + lane;
                yr[d] = (r[k] - mu) * rs * lng[m * 256 + d] + lnb[m * 256 + d];
            }
        }
    }
}

// =====================================================================
// Kernel 2: FF over y: out = y + f2( gelu(f1(y)) )
// grid (512, 4), 64 batch rows per block, hf chunked by 256
// =====================================================================
#define SM2_Y   0          // [64][256]
#define SM2_HF  16384      // [64][256]
#define SM2_WT  32768      // [32][260]
#define SM2_FLOATS 41088
#define SM2_BYTES  (SM2_FLOATS * 4)

__global__ __launch_bounds__(TPB, 1)
void gcma_part2(const float* __restrict__ f1w, const float* __restrict__ f1b,
                const float* __restrict__ f2w, const float* __restrict__ f2b,
                float* __restrict__ out)
{
    extern __shared__ float sm[];
    float* sY  = sm + SM2_Y;
    float* sHF = sm + SM2_HF;
    float* sWT = sm + SM2_WT;

    const int tid = threadIdx.x;
    const int m   = blockIdx.y;
    const int b0  = blockIdx.x * 64;

    const int rowg = tid >> 5;   // warp id, 8 rows each
    const int colg = tid & 31;   // 8 cols each

    // load y tile [64 rows][256]
    for (int idx = tid; idx < 4096; idx += TPB) {
        const int r = idx >> 6, q = idx & 63;
        *reinterpret_cast<float4*>(sY + r * 256 + q * 4) =
            *reinterpret_cast<const float4*>(g_y + ((size_t)(b0 + r) * 4 + m) * 256 + q * 4);
    }

    u64 facc[8][4];
#pragma unroll
    for (int i = 0; i < 8; ++i)
#pragma unroll
        for (int j = 0; j < 4; ++j) facc[i][j] = 0ULL;

    for (int ch = 0; ch < 4; ++ch) {
        // ---- FF1 chunk: hf[:, ch*256 .. +255] ----
        u64 hacc[8][4];
#pragma unroll
        for (int i = 0; i < 8; ++i)
#pragma unroll
            for (int j = 0; j < 4; ++j) hacc[i][j] = 0ULL;
        const float* W1 = f1w + (size_t)m * 262144 + (size_t)ch * 65536;
        for (int dt = 0; dt < 8; ++dt) {
            __syncthreads();
            ldW32(W1, 256, 256, dt * 32, sWT, tid);
            __syncthreads();
            mma64b(sY + rowg * 8 * 256 + dt * 32, 256, sWT, hacc, colg);
        }
        // bias + exact GELU -> sHF
        {
            const float* b1 = f1b + m * 1024 + ch * 256 + colg * 8;
            float bl[8];
#pragma unroll
            for (int j = 0; j < 8; ++j) bl[j] = b1[j];
#pragma unroll
            for (int i = 0; i < 8; ++i) {
                const int r = rowg * 8 + i;
                const float2 p0 = unpk(hacc[i][0]), p1 = unpk(hacc[i][1]);
                const float2 p2 = unpk(hacc[i][2]), p3 = unpk(hacc[i][3]);
                float v[8] = {p0.x + bl[0], p0.y + bl[1], p1.x + bl[2], p1.y + bl[3],
                              p2.x + bl[4], p2.y + bl[5], p3.x + bl[6], p3.y + bl[7]};
#pragma unroll
                for (int j = 0; j < 8; ++j)
                    v[j] = 0.5f * v[j] * (1.f + erff(v[j] * 0.7071067811865476f));
                *reinterpret_cast<float4*>(sHF + r * 256 + colg * 8) =
                    make_float4(v[0], v[1], v[2], v[3]);
                *reinterpret_cast<float4*>(sHF + r * 256 + colg * 8 + 4) =
                    make_float4(v[4], v[5], v[6], v[7]);
            }
        }
        // ---- FF2 partial ----
        const float* W2 = f2w + (size_t)m * 262144;
        for (int dt = 0; dt < 8; ++dt) {
            __syncthreads();
            ldW32(W2, 256, 1024, ch * 256 + dt * 32, sWT, tid);
            __syncthreads();
            mma64b(sHF + rowg * 8 * 256 + dt * 32, 256, sWT, facc, colg);
        }
    }

    // ---- epilogue: out = y + ff + f2b ----
    {
        float bl[8];
        const float* b2 = f2b + m * 256 + colg * 8;
#pragma unroll
        for (int j = 0; j < 8; ++j) bl[j] = b2[j];
#pragma unroll
        for (int i = 0; i < 8; ++i) {
            const int r = rowg * 8 + i;
            const float4 y0 = *reinterpret_cast<const float4*>(sY + r * 256 + colg * 8);
            const float4 y1 = *reinterpret_cast<const float4*>(sY + r * 256 + colg * 8 + 4);
            const float2 p0 = unpk(facc[i][0]), p1 = unpk(facc[i][1]);
            const float2 p2 = unpk(facc[i][2]), p3 = unpk(facc[i][3]);
            float* op = out + ((size_t)(b0 + r) * 4 + m) * 256 + colg * 8;
            *reinterpret_cast<float4*>(op) =
                make_float4(y0.x + p0.x + bl[0], y0.y + p0.y + bl[1],
                            y0.z + p1.x + bl[2], y0.w + p1.y + bl[3]);
            *reinterpret_cast<float4*>(op + 4) =
                make_float4(y1.x + p2.x + bl[4], y1.y + p2.y + bl[5],
                            y1.z + p3.x + bl[6], y1.w + p3.y + bl[7]);
        }
    }
}

extern "C" void kernel_launch(void* const* d_in, const int* in_sizes, int n_in,
                              void* d_out, int out_size) {
    const float* x   = (const float*)d_in[0];
    const float* Wq  = (const float*)d_in[1];
    const float* bq  = (const float*)d_in[2];
    const float* Wk  = (const float*)d_in[3];
    const float* bk  = (const float*)d_in[4];
    const float* Wv  = (const float*)d_in[5];
    const float* bv  = (const float*)d_in[6];
    const float* Wo  = (const float*)d_in[7];
    const float* bo  = (const float*)d_in[8];
    const float* g1w = (const float*)d_in[9];
    const float* g1b = (const float*)d_in[10];
    const float* g2w = (const float*)d_in[11];
    const float* g2b = (const float*)d_in[12];
    const float* lng = (const float*)d_in[13];
    const float* lnb = (const float*)d_in[14];
    const float* f1w = (const float*)d_in[15];
    const float* f1b = (const float*)d_in[16];
    const float* f2w = (const float*)d_in[17];
    const float* f2b = (const float*)d_in[18];
    float* out = (float*)d_out;

    cudaFuncSetAttribute(gcma_part1, cudaFuncAttributeMaxDynamicSharedMemorySize, SM1_BYTES);
    cudaFuncSetAttribute(gcma_part2, cudaFuncAttributeMaxDynamicSharedMemorySize, SM2_BYTES);

    dim3 grid1(32768 / 16, 4, 1);
    gcma_part1<<<grid1, TPB, SM1_BYTES>>>(x, Wq, bq, Wk, bk, Wv, bv, Wo, bo,
                                          g1w, g1b, g2w, g2b, lng, lnb, out);
    dim3 grid2(32768 / 64, 4, 1);
    gcma_part2<<<grid2, TPB, SM2_BYTES>>>(f1w, f1b, f2w, f2b, out);
}

// round 5
// speedup vs baseline: 1.2545x; 1.1006x over previous
#include <cuda_runtime.h>
#include <math.h>

typedef unsigned long long u64;

#define TPB 512
#define PW 260     // pitch of transposed W tile [32 d][cols<=256] (floats)

#define OUT_GATE_BASE 33554432UL   // B*M*D

// y scratch: [B,M,D] fp32 = 128MB
__device__ float g_y[32768u * 4u * 256u];

// ---------- packed fp32 helpers (Blackwell f32x2) ----------
static __device__ __forceinline__ u64 ffma2(u64 a, u64 b, u64 c) {
    u64 d;
    asm("fma.rn.f32x2 %0, %1, %2, %3;" : "=l"(d) : "l"(a), "l"(b), "l"(c));
    return d;
}
static __device__ __forceinline__ u64 dup2(float a) {
    u64 d;
    asm("mov.b64 %0, {%1, %1};" : "=l"(d) : "f"(a));
    return d;
}
static __device__ __forceinline__ float2 unpk(u64 p) {
    float2 r;
    asm("mov.b64 {%0, %1}, %2;" : "=f"(r.x), "=f"(r.y) : "l"(p));
    return r;
}
static __device__ __forceinline__ float comp4(const float4& v, int dd) {
    return dd == 0 ? v.x : dd == 1 ? v.y : dd == 2 ? v.z : v.w;
}

// ---------- W tile prefetch (regs) + transpose store to smem ----------
// tile = W[c][c0..c0+31] for c in [0, NIT*TPB/8); NIT*TPB == ncols*8
template<int NIT>
struct Wreg { float4 v[NIT]; };

template<int NIT>
static __device__ __forceinline__ void ldgW(const float* __restrict__ W, int ldw, int c0,
                                            Wreg<NIT>& r, int tid) {
#pragma unroll
    for (int k = 0; k < NIT; ++k) {
        const int idx = tid + k * TPB;
        const int c = idx >> 3, q = idx & 7;
        r.v[k] = *reinterpret_cast<const float4*>(W + (size_t)c * ldw + c0 + (q << 2));
    }
}

template<int NIT>
static __device__ __forceinline__ void stsW(float* sWT, const Wreg<NIT>& r, int tid) {
#pragma unroll
    for (int k = 0; k < NIT; ++k) {
        const int idx = tid + k * TPB;
        const int c = idx >> 3, q = idx & 7;
        const int d = q << 2;
        sWT[(d + 0) * PW + c] = r.v[k].x;
        sWT[(d + 1) * PW + c] = r.v[k].y;
        sWT[(d + 2) * PW + c] = r.v[k].z;
        sWT[(d + 3) * PW + c] = r.v[k].w;
    }
}

// ---------- mma: 64 rows x 256 cols, 512 threads ----------
// warp w -> rows w*4..+3 ; lane colg -> cols {colg*4..+3, 128+colg*4..+3}
static __device__ __forceinline__ void mma64b(const float* __restrict__ aRow, int lda,
                                              const float* __restrict__ sWT,
                                              u64 acc[4][4], int colg) {
#pragma unroll
    for (int d4 = 0; d4 < 8; ++d4) {
        float4 a4[4];
#pragma unroll
        for (int i = 0; i < 4; ++i)
            a4[i] = *reinterpret_cast<const float4*>(aRow + i * lda + (d4 << 2));
#pragma unroll
        for (int dd = 0; dd < 4; ++dd) {
            const int d = (d4 << 2) + dd;
            const ulonglong2 w0 = *reinterpret_cast<const ulonglong2*>(sWT + d * PW + (colg << 2));
            const ulonglong2 w1 = *reinterpret_cast<const ulonglong2*>(sWT + d * PW + 128 + (colg << 2));
#pragma unroll
            for (int i = 0; i < 4; ++i) {
                const u64 ad = dup2(comp4(a4[i], dd));
                acc[i][0] = ffma2(ad, w0.x, acc[i][0]);
                acc[i][1] = ffma2(ad, w0.y, acc[i][1]);
                acc[i][2] = ffma2(ad, w1.x, acc[i][2]);
                acc[i][3] = ffma2(ad, w1.y, acc[i][3]);
            }
        }
    }
}

// ---------- mma: 16 rows x 256 cols, 512 threads ----------
// g = tid>>7 -> rows g*4..+3 ; cp = tid&127 -> cols cp*2, cp*2+1
static __device__ __forceinline__ void mma16b(const float* __restrict__ aRow, int lda,
                                              const float* __restrict__ sWT,
                                              u64 acc[4], int cp) {
#pragma unroll
    for (int d4 = 0; d4 < 8; ++d4) {
        float4 a4[4];
#pragma unroll
        for (int i = 0; i < 4; ++i)
            a4[i] = *reinterpret_cast<const float4*>(aRow + i * lda + (d4 << 2));
#pragma unroll
        for (int dd = 0; dd < 4; ++dd) {
            const int d = (d4 << 2) + dd;
            const u64 w = *reinterpret_cast<const u64*>(sWT + d * PW + cp * 2);
#pragma unroll
            for (int i = 0; i < 4; ++i)
                acc[i] = ffma2(dup2(comp4(a4[i], dd)), w, acc[i]);
        }
    }
}

// ---------- mma: 16 rows x 64 cols (gate1), 512 threads ----------
// g8 = tid>>6 -> rows g8*2..+1 ; col = tid&63
static __device__ __forceinline__ void mmagb(const float* __restrict__ aRow, int lda,
                                             const float* __restrict__ sWT,
                                             float gacc[2], int col) {
#pragma unroll
    for (int d4 = 0; d4 < 8; ++d4) {
        const float4 a0 = *reinterpret_cast<const float4*>(aRow + (d4 << 2));
        const float4 a1 = *reinterpret_cast<const float4*>(aRow + lda + (d4 << 2));
#pragma unroll
        for (int dd = 0; dd < 4; ++dd) {
            const float w = sWT[((d4 << 2) + dd) * PW + col];
            gacc[0] = fmaf(comp4(a0, dd), w, gacc[0]);
            gacc[1] = fmaf(comp4(a1, dd), w, gacc[1]);
        }
    }
}

// =====================================================================
// Kernel 1: KV proj + attention + Wo + gate + LayerNorm -> g_y, gate->out
// grid (2048, 4), 16 batch elements per block, 512 threads
// =====================================================================
#define SM1_X    0        // [64][256]
#define SM1_WT   16384    // [32][260]
#define SM1_Q    24704    // [16][256]  (Q, then Oh)
#define SM1_KV   28800    // [64][256]  (K, then V)
#define SM1_P    45184    // [16][8][4] probs
#define SM1_AO   45696    // [16][256]
#define SM1_GH   49792    // [16][64]
#define SM1_GATE 50816    // [16]
#define SM1_FLOATS 50832
#define SM1_BYTES  (SM1_FLOATS * 4)

__global__ __launch_bounds__(TPB, 1)
void gcma_part1(const float* __restrict__ x,
                const float* __restrict__ Wq, const float* __restrict__ bq,
                const float* __restrict__ Wk, const float* __restrict__ bk,
                const float* __restrict__ Wv, const float* __restrict__ bv,
                const float* __restrict__ Wo, const float* __restrict__ bo,
                const float* __restrict__ g1w, const float* __restrict__ g1b,
                const float* __restrict__ g2w, const float* __restrict__ g2b,
                const float* __restrict__ lng, const float* __restrict__ lnb,
                float* __restrict__ out)
{
    extern __shared__ float sm[];
    float* sX    = sm + SM1_X;
    float* sWT   = sm + SM1_WT;
    float* sQ    = sm + SM1_Q;
    float* sKV   = sm + SM1_KV;
    float* sP    = sm + SM1_P;
    float* sAO   = sm + SM1_AO;
    float* sGH   = sm + SM1_GH;
    float* sGate = sm + SM1_GATE;

    const int tid = threadIdx.x;
    const int m   = blockIdx.y;
    const int b0  = blockIdx.x * 16;
    const long g0 = (long)b0 * 4;

    const int warp = tid >> 5;    // 0..15
    const int colg = tid & 31;
    const int g    = tid >> 7;    // 0..3
    const int cp   = tid & 127;
    const int g8   = tid >> 6;    // 0..7
    const int col  = tid & 63;

    // ---- stage X block [64 rows][256] row-major ----
    {
        const float* Xblk = x + (size_t)g0 * 256;
        for (int idx = tid; idx < 4096; idx += TPB) {
            const int r = idx >> 6, q = idx & 63;
            *reinterpret_cast<float4*>(sX + r * 256 + q * 4) =
                *reinterpret_cast<const float4*>(Xblk + r * 256 + q * 4);
        }
    }

    // ---- Q: [16 x 256], scaled ----
    {
        const float* W    = Wq + (size_t)m * 65536;
        const float* bias = bq + m * 256;
        Wreg<4> wr;
        ldgW<4>(W, 256, 0, wr, tid);
        u64 acc[4] = {0ULL, 0ULL, 0ULL, 0ULL};
        const float* aRow = sX + m * 256 + g * 4 * 1024;
        for (int dt = 0; dt < 8; ++dt) {
            __syncthreads();
            stsW<4>(sWT, wr, tid);
            if (dt < 7) ldgW<4>(W, 256, (dt + 1) * 32, wr, tid);
            __syncthreads();
            mma16b(aRow + dt * 32, 1024, sWT, acc, cp);
        }
        const float bc0 = bias[cp * 2], bc1 = bias[cp * 2 + 1];
#pragma unroll
        for (int i = 0; i < 4; ++i) {
            const float2 p = unpk(acc[i]);
            *reinterpret_cast<float2*>(sQ + (g * 4 + i) * 256 + cp * 2) =
                make_float2((p.x + bc0) * 0.17677669529663687f,
                            (p.y + bc1) * 0.17677669529663687f);
        }
    }

    // ---- K: [64 x 256] -> sKV ----
    {
        const float* W    = Wk + (size_t)m * 65536;
        const float* bias = bk + m * 256;
        Wreg<4> wr;
        ldgW<4>(W, 256, 0, wr, tid);
        u64 acc[4][4];
#pragma unroll
        for (int i = 0; i < 4; ++i)
#pragma unroll
            for (int j = 0; j < 4; ++j) acc[i][j] = 0ULL;
        const float* aRow = sX + warp * 4 * 256;
        for (int dt = 0; dt < 8; ++dt) {
            __syncthreads();
            stsW<4>(sWT, wr, tid);
            if (dt < 7) ldgW<4>(W, 256, (dt + 1) * 32, wr, tid);
            __syncthreads();
            mma64b(aRow + dt * 32, 256, sWT, acc, colg);
        }
        float bl0[4], bl1[4];
#pragma unroll
        for (int j = 0; j < 4; ++j) { bl0[j] = bias[colg * 4 + j]; bl1[j] = bias[128 + colg * 4 + j]; }
#pragma unroll
        for (int i = 0; i < 4; ++i) {
            const int r = warp * 4 + i;
            const float2 pa = unpk(acc[i][0]), pb = unpk(acc[i][1]);
            const float2 pc = unpk(acc[i][2]), pd = unpk(acc[i][3]);
            *reinterpret_cast<float4*>(sKV + r * 256 + colg * 4) =
                make_float4(pa.x + bl0[0], pa.y + bl0[1], pb.x + bl0[2], pb.y + bl0[3]);
            *reinterpret_cast<float4*>(sKV + r * 256 + 128 + colg * 4) =
                make_float4(pc.x + bl1[0], pc.y + bl1[1], pd.x + bl1[2], pd.y + bl1[3]);
        }
    }
    __syncthreads();

    // ---- scores + softmax -> probs sP ----
    if (tid < 128) {
        const int bl = tid >> 3, h = tid & 7;
        const float* qp = sQ + bl * 256 + h * 32;
        float q[32];
#pragma unroll
        for (int i = 0; i < 32; ++i) q[i] = qp[i];
        float s[4];
#pragma unroll
        for (int n = 0; n < 4; ++n) {
            const float* kp = sKV + (bl * 4 + n) * 256 + h * 32;
            float dot = 0.f;
#pragma unroll
            for (int i = 0; i < 32; ++i) dot = fmaf(q[i], kp[i], dot);
            s[n] = dot;
        }
        const float mx = fmaxf(fmaxf(s[0], s[1]), fmaxf(s[2], s[3]));
        float e[4], se = 0.f;
#pragma unroll
        for (int n = 0; n < 4; ++n) { e[n] = expf(s[n] - mx); se += e[n]; }
        const float inv = 1.f / se;
#pragma unroll
        for (int n = 0; n < 4; ++n) sP[tid * 4 + n] = e[n] * inv;
    }

    // ---- V: [64 x 256] -> sKV (overwrites K after barriers) ----
    {
        const float* W    = Wv + (size_t)m * 65536;
        const float* bias = bv + m * 256;
        Wreg<4> wr;
        ldgW<4>(W, 256, 0, wr, tid);
        u64 acc[4][4];
#pragma unroll
        for (int i = 0; i < 4; ++i)
#pragma unroll
            for (int j = 0; j < 4; ++j) acc[i][j] = 0ULL;
        const float* aRow = sX + warp * 4 * 256;
        for (int dt = 0; dt < 8; ++dt) {
            __syncthreads();
            stsW<4>(sWT, wr, tid);
            if (dt < 7) ldgW<4>(W, 256, (dt + 1) * 32, wr, tid);
            __syncthreads();
            mma64b(aRow + dt * 32, 256, sWT, acc, colg);
        }
        __syncthreads();   // K fully consumed (scores done) before overwrite
        float bl0[4], bl1[4];
#pragma unroll
        for (int j = 0; j < 4; ++j) { bl0[j] = bias[colg * 4 + j]; bl1[j] = bias[128 + colg * 4 + j]; }
#pragma unroll
        for (int i = 0; i < 4; ++i) {
            const int r = warp * 4 + i;
            const float2 pa = unpk(acc[i][0]), pb = unpk(acc[i][1]);
            const float2 pc = unpk(acc[i][2]), pd = unpk(acc[i][3]);
            *reinterpret_cast<float4*>(sKV + r * 256 + colg * 4) =
                make_float4(pa.x + bl0[0], pa.y + bl0[1], pb.x + bl0[2], pb.y + bl0[3]);
            *reinterpret_cast<float4*>(sKV + r * 256 + 128 + colg * 4) =
                make_float4(pc.x + bl1[0], pc.y + bl1[1], pd.x + bl1[2], pd.y + bl1[3]);
        }
    }
    __syncthreads();

    // ---- Oh = P @ V -> sQ (overwrites Q) ----
    if (tid < 128) {
        const int bl = tid >> 3, h = tid & 7;
        float o[32];
#pragma unroll
        for (int i = 0; i < 32; ++i) o[i] = 0.f;
#pragma unroll
        for (int n = 0; n < 4; ++n) {
            const float p = sP[tid * 4 + n];
            const float* vp = sKV + (bl * 4 + n) * 256 + h * 32;
#pragma unroll
            for (int i = 0; i < 32; ++i) o[i] = fmaf(p, vp[i], o[i]);
        }
        float* op = sQ + bl * 256 + h * 32;
#pragma unroll
        for (int i = 0; i < 32; ++i) op[i] = o[i];
    }

    // ---- Wo: attn_out [16 x 256] -> sAO ----
    {
        const float* W    = Wo + (size_t)m * 65536;
        const float* bias = bo + m * 256;
        Wreg<4> wr;
        ldgW<4>(W, 256, 0, wr, tid);
        u64 acc[4] = {0ULL, 0ULL, 0ULL, 0ULL};
        const float* aRow = sQ + g * 4 * 256;
        for (int dt = 0; dt < 8; ++dt) {
            __syncthreads();
            stsW<4>(sWT, wr, tid);
            if (dt < 7) ldgW<4>(W, 256, (dt + 1) * 32, wr, tid);
            __syncthreads();
            mma16b(aRow + dt * 32, 256, sWT, acc, cp);
        }
        const float bc0 = bias[cp * 2], bc1 = bias[cp * 2 + 1];
#pragma unroll
        for (int i = 0; i < 4; ++i) {
            const float2 p = unpk(acc[i]);
            *reinterpret_cast<float2*>(sAO + (g * 4 + i) * 256 + cp * 2) =
                make_float2(p.x + bc0, p.y + bc1);
        }
    }

    // ---- gate layer 1: tanh([x_m ; AO] @ g1w^T) [16 x 64] ----
    {
        const float* W = g1w + (size_t)m * 32768;   // [64][512]
        Wreg<1> wr;
        ldgW<1>(W, 512, 0, wr, tid);
        float gacc[2] = {0.f, 0.f};
        for (int dt = 0; dt < 16; ++dt) {
            __syncthreads();
            stsW<1>(sWT, wr, tid);
            if (dt < 15) ldgW<1>(W, 512, (dt + 1) * 32, wr, tid);
            __syncthreads();
            if (dt < 8)
                mmagb(sX + m * 256 + g8 * 2 * 1024 + dt * 32, 1024, sWT, gacc, col);
            else
                mmagb(sAO + g8 * 2 * 256 + (dt - 8) * 32, 256, sWT, gacc, col);
        }
        const float gb = g1b[m * 64 + col];
        sGH[(g8 * 2 + 0) * 64 + col] = tanhf(gacc[0] + gb);
        sGH[(g8 * 2 + 1) * 64 + col] = tanhf(gacc[1] + gb);
    }
    __syncthreads();

    // ---- gate layer 2 + sigmoid ----
    if (tid < 16) {
        const float* g2 = g2w + m * 64;
        float dot = g2b[m];
#pragma unroll 8
        for (int j = 0; j < 64; ++j) dot = fmaf(sGH[tid * 64 + j], g2[j], dot);
        const float gate = 1.f / (1.f + expf(-dot));
        sGate[tid] = gate;
        out[OUT_GATE_BASE + (size_t)(b0 + tid) * 4 + m] = gate;
    }
    __syncthreads();

    // ---- residual + LayerNorm -> g_y (one warp per batch row) ----
    {
        const int lane = tid & 31;
        const int bl   = warp;   // 16 warps : 16 rows
        const float* xr = sX + (bl * 4 + m) * 256;
        const float gate = sGate[bl];
        float r[8];
        float sum = 0.f;
#pragma unroll
        for (int k = 0; k < 8; ++k) {
            const int d = k * 32 + lane;
            r[k] = xr[d] + gate * sAO[bl * 256 + d];
            sum += r[k];
        }
#pragma unroll
        for (int o = 16; o; o >>= 1) sum += __shfl_xor_sync(0xffffffffu, sum, o);
        const float mu = sum * (1.f / 256.f);
        float var = 0.f;
#pragma unroll
        for (int k = 0; k < 8; ++k) { const float t = r[k] - mu; var = fmaf(t, t, var); }
#pragma unroll
        for (int o = 16; o; o >>= 1) var += __shfl_xor_sync(0xffffffffu, var, o);
        const float rs = rsqrtf(var * (1.f / 256.f) + 1e-5f);
        float* yr = g_y + (size_t)(g0 + bl * 4 + m) * 256;
#pragma unroll
        for (int k = 0; k < 8; ++k) {
            const int d = k * 32 + lane;
            yr[d] = (r[k] - mu) * rs * lng[m * 256 + d] + lnb[m * 256 + d];
        }
    }
}

// =====================================================================
// Kernel 2: FF over y: out = y + f2( gelu(f1(y)) )
// grid (512, 4), 64 batch rows per block, 512 threads, hf chunked by 256
// =====================================================================
#define SM2_Y   0          // [64][256]
#define SM2_HF  16384      // [64][256]
#define SM2_WT  32768      // [32][260]
#define SM2_FLOATS 41088
#define SM2_BYTES  (SM2_FLOATS * 4)

__global__ __launch_bounds__(TPB, 1)
void gcma_part2(const float* __restrict__ f1w, const float* __restrict__ f1b,
                const float* __restrict__ f2w, const float* __restrict__ f2b,
                float* __restrict__ out)
{
    extern __shared__ float sm[];
    float* sY  = sm + SM2_Y;
    float* sHF = sm + SM2_HF;
    float* sWT = sm + SM2_WT;

    const int tid = threadIdx.x;
    const int m   = blockIdx.y;
    const int b0  = blockIdx.x * 64;

    const int warp = tid >> 5;   // 0..15, 4 rows each
    const int colg = tid & 31;   // cols {colg*4..+3, 128+colg*4..+3}

    // load y tile [64 rows][256]
    for (int idx = tid; idx < 4096; idx += TPB) {
        const int r = idx >> 6, q = idx & 63;
        *reinterpret_cast<float4*>(sY + r * 256 + q * 4) =
            *reinterpret_cast<const float4*>(g_y + ((size_t)(b0 + r) * 4 + m) * 256 + q * 4);
    }

    u64 facc[4][4];
#pragma unroll
    for (int i = 0; i < 4; ++i)
#pragma unroll
        for (int j = 0; j < 4; ++j) facc[i][j] = 0ULL;

    const float* aY  = sY  + warp * 4 * 256;
    const float* aHF = sHF + warp * 4 * 256;

    for (int ch = 0; ch < 4; ++ch) {
        // ---- FF1 chunk: hf[:, ch*256 .. +255] ----
        u64 hacc[4][4];
#pragma unroll
        for (int i = 0; i < 4; ++i)
#pragma unroll
            for (int j = 0; j < 4; ++j) hacc[i][j] = 0ULL;
        {
            const float* W1 = f1w + (size_t)m * 262144 + (size_t)ch * 65536;
            Wreg<4> wr;
            ldgW<4>(W1, 256, 0, wr, tid);
            for (int dt = 0; dt < 8; ++dt) {
                __syncthreads();
                stsW<4>(sWT, wr, tid);
                if (dt < 7) ldgW<4>(W1, 256, (dt + 1) * 32, wr, tid);
                __syncthreads();
                mma64b(aY + dt * 32, 256, sWT, hacc, colg);
            }
        }
        __syncthreads();   // previous FF2 reads of sHF complete before overwrite
        // bias + exact GELU -> sHF
        {
            const float* b1 = f1b + m * 1024 + ch * 256;
            float bl0[4], bl1[4];
#pragma unroll
            for (int j = 0; j < 4; ++j) { bl0[j] = b1[colg * 4 + j]; bl1[j] = b1[128 + colg * 4 + j]; }
#pragma unroll
            for (int i = 0; i < 4; ++i) {
                const int r = warp * 4 + i;
                const float2 pa = unpk(hacc[i][0]), pb = unpk(hacc[i][1]);
                const float2 pc = unpk(hacc[i][2]), pd = unpk(hacc[i][3]);
                float v0[4] = {pa.x + bl0[0], pa.y + bl0[1], pb.x + bl0[2], pb.y + bl0[3]};
                float v1[4] = {pc.x + bl1[0], pc.y + bl1[1], pd.x + bl1[2], pd.y + bl1[3]};
#pragma unroll
                for (int j = 0; j < 4; ++j) {
                    v0[j] = 0.5f * v0[j] * (1.f + erff(v0[j] * 0.7071067811865476f));
                    v1[j] = 0.5f * v1[j] * (1.f + erff(v1[j] * 0.7071067811865476f));
                }
                *reinterpret_cast<float4*>(sHF + r * 256 + colg * 4) =
                    make_float4(v0[0], v0[1], v0[2], v0[3]);
                *reinterpret_cast<float4*>(sHF + r * 256 + 128 + colg * 4) =
                    make_float4(v1[0], v1[1], v1[2], v1[3]);
            }
        }
        // ---- FF2 partial ----
        {
            const float* W2 = f2w + (size_t)m * 262144;
            Wreg<4> wr;
            ldgW<4>(W2, 1024, ch * 256, wr, tid);
            for (int dt = 0; dt < 8; ++dt) {
                __syncthreads();
                stsW<4>(sWT, wr, tid);
                if (dt < 7) ldgW<4>(W2, 1024, ch * 256 + (dt + 1) * 32, wr, tid);
                __syncthreads();
                mma64b(aHF + dt * 32, 256, sWT, facc, colg);
            }
        }
    }

    // ---- epilogue: out = y + ff + f2b ----
    {
        const float* b2 = f2b + m * 256;
        float bl0[4], bl1[4];
#pragma unroll
        for (int j = 0; j < 4; ++j) { bl0[j] = b2[colg * 4 + j]; bl1[j] = b2[128 + colg * 4 + j]; }
#pragma unroll
        for (int i = 0; i < 4; ++i) {
            const int r = warp * 4 + i;
            const float4 y0 = *reinterpret_cast<const float4*>(sY + r * 256 + colg * 4);
            const float4 y1 = *reinterpret_cast<const float4*>(sY + r * 256 + 128 + colg * 4);
            const float2 pa = unpk(facc[i][0]), pb = unpk(facc[i][1]);
            const float2 pc = unpk(facc[i][2]), pd = unpk(facc[i][3]);
            float* op = out + ((size_t)(b0 + r) * 4 + m) * 256;
            *reinterpret_cast<float4*>(op + colg * 4) =
                make_float4(y0.x + pa.x + bl0[0], y0.y + pa.y + bl0[1],
                            y0.z + pb.x + bl0[2], y0.w + pb.y + bl0[3]);
            *reinterpret_cast<float4*>(op + 128 + colg * 4) =
                make_float4(y1.x + pc.x + bl1[0], y1.y + pc.y + bl1[1],
                            y1.z + pd.x + bl1[2], y1.w + pd.y + bl1[3]);
        }
    }
}

extern "C" void kernel_launch(void* const* d_in, const int* in_sizes, int n_in,
                              void* d_out, int out_size) {
    const float* x   = (const float*)d_in[0];
    const float* Wq  = (const float*)d_in[1];
    const float* bq  = (const float*)d_in[2];
    const float* Wk  = (const float*)d_in[3];
    const float* bk  = (const float*)d_in[4];
    const float* Wv  = (const float*)d_in[5];
    const float* bv  = (const float*)d_in[6];
    const float* Wo  = (const float*)d_in[7];
    const float* bo  = (const float*)d_in[8];
    const float* g1w = (const float*)d_in[9];
    const float* g1b = (const float*)d_in[10];
    const float* g2w = (const float*)d_in[11];
    const float* g2b = (const float*)d_in[12];
    const float* lng = (const float*)d_in[13];
    const float* lnb = (const float*)d_in[14];
    const float* f1w = (const float*)d_in[15];
    const float* f1b = (const float*)d_in[16];
    const float* f2w = (const float*)d_in[17];
    const float* f2b = (const float*)d_in[18];
    float* out = (float*)d_out;

    cudaFuncSetAttribute(gcma_part1, cudaFuncAttributeMaxDynamicSharedMemorySize, SM1_BYTES);
    cudaFuncSetAttribute(gcma_part2, cudaFuncAttributeMaxDynamicSharedMemorySize, SM2_BYTES);

    dim3 grid1(32768 / 16, 4, 1);
    gcma_part1<<<grid1, TPB, SM1_BYTES>>>(x, Wq, bq, Wk, bk, Wv, bv, Wo, bo,
                                          g1w, g1b, g2w, g2b, lng, lnb, out);
    dim3 grid2(32768 / 64, 4, 1);
    gcma_part2<<<grid2, TPB, SM2_BYTES>>>(f1w, f1b, f2w, f2b, out);
}

// round 6
// speedup vs baseline: 1.4120x; 1.1256x over previous
#include <cuda_runtime.h>
#include <math.h>

typedef unsigned long long u64;

#define TPB 256
#define PW 260     // pitch of transposed W tile; PW%32==4 -> conflict-free STS.128

#define OUT_GATE_BASE 33554432UL   // B*M*D

// y scratch: [B,M,D] fp32 = 128MB
__device__ float g_y[32768u * 4u * 256u];

// ---------- packed fp32 helpers (Blackwell f32x2) ----------
static __device__ __forceinline__ u64 ffma2(u64 a, u64 b, u64 c) {
    u64 d;
    asm("fma.rn.f32x2 %0, %1, %2, %3;" : "=l"(d) : "l"(a), "l"(b), "l"(c));
    return d;
}
static __device__ __forceinline__ u64 dup2(float a) {
    u64 d;
    asm("mov.b64 %0, {%1, %1};" : "=l"(d) : "f"(a));
    return d;
}
static __device__ __forceinline__ float2 unpk(u64 p) {
    float2 r;
    asm("mov.b64 {%0, %1}, %2;" : "=f"(r.x), "=f"(r.y) : "l"(p));
    return r;
}
static __device__ __forceinline__ float comp4(const float4& v, int dd) {
    return dd == 0 ? v.x : dd == 1 ? v.y : dd == 2 ? v.z : v.w;
}

// ---------- W tile prefetch, d-major: iter idx -> (c4 = idx>>5, d = idx&31) ----------
// loads W[c4*4 + i][k0 + d] for i=0..3 (each LDG.32 coalesced 128B across the warp)
template<int NIT>
struct Wreg { float f[NIT][4]; };

template<int NIT>
static __device__ __forceinline__ void ldgW(const float* __restrict__ W, int ldw, int k0,
                                            Wreg<NIT>& r, int tid) {
#pragma unroll
    for (int k = 0; k < NIT; ++k) {
        const int idx = tid + k * TPB;
        const int d = idx & 31, c4 = idx >> 5;
#pragma unroll
        for (int i = 0; i < 4; ++i)
            r.f[k][i] = W[(size_t)(c4 * 4 + i) * ldw + k0 + d];
    }
}

// STS.128 to sWT[d*PW + c4*4] — conflict-free (PW%32==4)
template<int NIT>
static __device__ __forceinline__ void stsW(float* sWT, const Wreg<NIT>& r, int tid) {
#pragma unroll
    for (int k = 0; k < NIT; ++k) {
        const int idx = tid + k * TPB;
        const int d = idx & 31, c4 = idx >> 5;
        *reinterpret_cast<float4*>(sWT + d * PW + c4 * 4) =
            make_float4(r.f[k][0], r.f[k][1], r.f[k][2], r.f[k][3]);
    }
}

// ---------- mma: 64 rows x 256 cols, 256 threads, 8x8 thread tiles ----------
// warp -> rows warp*8..+7 ; lane colg -> cols {colg*4..+3, 128+colg*4..+3}
static __device__ __forceinline__ void mma64b(const float* __restrict__ aRow, int lda,
                                              const float* __restrict__ sWT,
                                              u64 acc[8][4], int colg) {
#pragma unroll
    for (int d4 = 0; d4 < 8; ++d4) {
        float4 a4[8];
#pragma unroll
        for (int i = 0; i < 8; ++i)
            a4[i] = *reinterpret_cast<const float4*>(aRow + i * lda + (d4 << 2));
#pragma unroll
        for (int dd = 0; dd < 4; ++dd) {
            const int d = (d4 << 2) + dd;
            const ulonglong2 w0 = *reinterpret_cast<const ulonglong2*>(sWT + d * PW + (colg << 2));
            const ulonglong2 w1 = *reinterpret_cast<const ulonglong2*>(sWT + d * PW + 128 + (colg << 2));
#pragma unroll
            for (int i = 0; i < 8; ++i) {
                const u64 ad = dup2(comp4(a4[i], dd));
                acc[i][0] = ffma2(ad, w0.x, acc[i][0]);
                acc[i][1] = ffma2(ad, w0.y, acc[i][1]);
                acc[i][2] = ffma2(ad, w1.x, acc[i][2]);
                acc[i][3] = ffma2(ad, w1.y, acc[i][3]);
            }
        }
    }
}

// ---------- mma: 16 rows x 256 cols, 256 threads ----------
// warp -> rows warp*2..+1 ; lane colg -> cols {colg*4..+3, 128+colg*4..+3}
static __device__ __forceinline__ void mma16b(const float* __restrict__ aRow, int lda,
                                              const float* __restrict__ sWT,
                                              u64 acc[2][4], int colg) {
#pragma unroll
    for (int d4 = 0; d4 < 8; ++d4) {
        float4 a4[2];
        a4[0] = *reinterpret_cast<const float4*>(aRow + (d4 << 2));
        a4[1] = *reinterpret_cast<const float4*>(aRow + lda + (d4 << 2));
#pragma unroll
        for (int dd = 0; dd < 4; ++dd) {
            const int d = (d4 << 2) + dd;
            const ulonglong2 w0 = *reinterpret_cast<const ulonglong2*>(sWT + d * PW + (colg << 2));
            const ulonglong2 w1 = *reinterpret_cast<const ulonglong2*>(sWT + d * PW + 128 + (colg << 2));
#pragma unroll
            for (int i = 0; i < 2; ++i) {
                const u64 ad = dup2(comp4(a4[i], dd));
                acc[i][0] = ffma2(ad, w0.x, acc[i][0]);
                acc[i][1] = ffma2(ad, w0.y, acc[i][1]);
                acc[i][2] = ffma2(ad, w1.x, acc[i][2]);
                acc[i][3] = ffma2(ad, w1.y, acc[i][3]);
            }
        }
    }
}

// ---------- mma: 16 rows x 64 cols (gate1), 256 threads ----------
// warp -> rows warp*2..+1 ; lane colg -> cols colg*2, colg*2+1 (packed u64 pair)
static __device__ __forceinline__ void mmagb(const float* __restrict__ aRow, int lda,
                                             const float* __restrict__ sWT,
                                             u64 gacc[2], int colg) {
#pragma unroll
    for (int d4 = 0; d4 < 8; ++d4) {
        const float4 a0 = *reinterpret_cast<const float4*>(aRow + (d4 << 2));
        const float4 a1 = *reinterpret_cast<const float4*>(aRow + lda + (d4 << 2));
#pragma unroll
        for (int dd = 0; dd < 4; ++dd) {
            const u64 w = *reinterpret_cast<const u64*>(sWT + ((d4 << 2) + dd) * PW + colg * 2);
            gacc[0] = ffma2(dup2(comp4(a0, dd)), w, gacc[0]);
            gacc[1] = ffma2(dup2(comp4(a1, dd)), w, gacc[1]);
        }
    }
}

// =====================================================================
// Kernel 1: KV proj + attention + Wo + gate + LayerNorm -> g_y, gate->out
// grid (2048, 4), 16 batch elements per block, 256 threads
// =====================================================================
#define SM1_X    0        // [64][256]
#define SM1_WT   16384    // [32][260]
#define SM1_Q    24704    // [16][256]  (Q, then Oh)
#define SM1_KV   28800    // [64][256]  (K, then V)
#define SM1_P    45184    // [16][8][4] probs
#define SM1_AO   45696    // [16][256]
#define SM1_GH   49792    // [16][64]
#define SM1_GATE 50816    // [16]
#define SM1_FLOATS 50832
#define SM1_BYTES  (SM1_FLOATS * 4)

__global__ __launch_bounds__(TPB, 1)
void gcma_part1(const float* __restrict__ x,
                const float* __restrict__ Wq, const float* __restrict__ bq,
                const float* __restrict__ Wk, const float* __restrict__ bk,
                const float* __restrict__ Wv, const float* __restrict__ bv,
                const float* __restrict__ Wo, const float* __restrict__ bo,
                const float* __restrict__ g1w, const float* __restrict__ g1b,
                const float* __restrict__ g2w, const float* __restrict__ g2b,
                const float* __restrict__ lng, const float* __restrict__ lnb,
                float* __restrict__ out)
{
    extern __shared__ float sm[];
    float* sX    = sm + SM1_X;
    float* sWT   = sm + SM1_WT;
    float* sQ    = sm + SM1_Q;
    float* sKV   = sm + SM1_KV;
    float* sP    = sm + SM1_P;
    float* sAO   = sm + SM1_AO;
    float* sGH   = sm + SM1_GH;
    float* sGate = sm + SM1_GATE;

    const int tid = threadIdx.x;
    const int m   = blockIdx.y;
    const int b0  = blockIdx.x * 16;
    const long g0 = (long)b0 * 4;

    const int warp = tid >> 5;    // 0..7
    const int colg = tid & 31;

    // ---- stage X block [64 rows][256] row-major ----
    {
        const float* Xblk = x + (size_t)g0 * 256;
        for (int idx = tid; idx < 4096; idx += TPB) {
            const int r = idx >> 6, q = idx & 63;
            *reinterpret_cast<float4*>(sX + r * 256 + q * 4) =
                *reinterpret_cast<const float4*>(Xblk + r * 256 + q * 4);
        }
    }

    // ---- Q: [16 x 256], scaled ----
    {
        const float* W    = Wq + (size_t)m * 65536;
        const float* bias = bq + m * 256;
        Wreg<8> wr;
        ldgW<8>(W, 256, 0, wr, tid);
        u64 acc[2][4];
#pragma unroll
        for (int i = 0; i < 2; ++i)
#pragma unroll
            for (int j = 0; j < 4; ++j) acc[i][j] = 0ULL;
        const float* aRow = sX + m * 256 + warp * 2 * 1024;
        for (int dt = 0; dt < 8; ++dt) {
            __syncthreads();
            stsW<8>(sWT, wr, tid);
            if (dt < 7) ldgW<8>(W, 256, (dt + 1) * 32, wr, tid);
            __syncthreads();
            mma16b(aRow + dt * 32, 1024, sWT, acc, colg);
        }
        float bl0[4], bl1[4];
#pragma unroll
        for (int j = 0; j < 4; ++j) { bl0[j] = bias[colg * 4 + j]; bl1[j] = bias[128 + colg * 4 + j]; }
#pragma unroll
        for (int i = 0; i < 2; ++i) {
            const int r = warp * 2 + i;
            const float2 pa = unpk(acc[i][0]), pb = unpk(acc[i][1]);
            const float2 pc = unpk(acc[i][2]), pd = unpk(acc[i][3]);
            const float s = 0.17677669529663687f;
            *reinterpret_cast<float4*>(sQ + r * 256 + colg * 4) =
                make_float4((pa.x + bl0[0]) * s, (pa.y + bl0[1]) * s,
                            (pb.x + bl0[2]) * s, (pb.y + bl0[3]) * s);
            *reinterpret_cast<float4*>(sQ + r * 256 + 128 + colg * 4) =
                make_float4((pc.x + bl1[0]) * s, (pc.y + bl1[1]) * s,
                            (pd.x + bl1[2]) * s, (pd.y + bl1[3]) * s);
        }
    }

    // ---- K: [64 x 256] -> sKV ----
    {
        const float* W    = Wk + (size_t)m * 65536;
        const float* bias = bk + m * 256;
        Wreg<8> wr;
        ldgW<8>(W, 256, 0, wr, tid);
        u64 acc[8][4];
#pragma unroll
        for (int i = 0; i < 8; ++i)
#pragma unroll
            for (int j = 0; j < 4; ++j) acc[i][j] = 0ULL;
        const float* aRow = sX + warp * 8 * 256;
        for (int dt = 0; dt < 8; ++dt) {
            __syncthreads();
            stsW<8>(sWT, wr, tid);
            if (dt < 7) ldgW<8>(W, 256, (dt + 1) * 32, wr, tid);
            __syncthreads();
            mma64b(aRow + dt * 32, 256, sWT, acc, colg);
        }
        float bl0[4], bl1[4];
#pragma unroll
        for (int j = 0; j < 4; ++j) { bl0[j] = bias[colg * 4 + j]; bl1[j] = bias[128 + colg * 4 + j]; }
#pragma unroll
        for (int i = 0; i < 8; ++i) {
            const int r = warp * 8 + i;
            const float2 pa = unpk(acc[i][0]), pb = unpk(acc[i][1]);
            const float2 pc = unpk(acc[i][2]), pd = unpk(acc[i][3]);
            *reinterpret_cast<float4*>(sKV + r * 256 + colg * 4) =
                make_float4(pa.x + bl0[0], pa.y + bl0[1], pb.x + bl0[2], pb.y + bl0[3]);
            *reinterpret_cast<float4*>(sKV + r * 256 + 128 + colg * 4) =
                make_float4(pc.x + bl1[0], pc.y + bl1[1], pd.x + bl1[2], pd.y + bl1[3]);
        }
    }
    __syncthreads();

    // ---- scores + softmax -> probs sP ----
    if (tid < 128) {
        const int bl = tid >> 3, h = tid & 7;
        const float* qp = sQ + bl * 256 + h * 32;
        float q[32];
#pragma unroll
        for (int i = 0; i < 32; ++i) q[i] = qp[i];
        float s[4];
#pragma unroll
        for (int n = 0; n < 4; ++n) {
            const float* kp = sKV + (bl * 4 + n) * 256 + h * 32;
            float dot = 0.f;
#pragma unroll
            for (int i = 0; i < 32; ++i) dot = fmaf(q[i], kp[i], dot);
            s[n] = dot;
        }
        const float mx = fmaxf(fmaxf(s[0], s[1]), fmaxf(s[2], s[3]));
        float e[4], se = 0.f;
#pragma unroll
        for (int n = 0; n < 4; ++n) { e[n] = expf(s[n] - mx); se += e[n]; }
        const float inv = 1.f / se;
#pragma unroll
        for (int n = 0; n < 4; ++n) sP[tid * 4 + n] = e[n] * inv;
    }

    // ---- V: [64 x 256] -> sKV (overwrites K after scores consumed) ----
    {
        const float* W    = Wv + (size_t)m * 65536;
        const float* bias = bv + m * 256;
        Wreg<8> wr;
        ldgW<8>(W, 256, 0, wr, tid);
        u64 acc[8][4];
#pragma unroll
        for (int i = 0; i < 8; ++i)
#pragma unroll
            for (int j = 0; j < 4; ++j) acc[i][j] = 0ULL;
        const float* aRow = sX + warp * 8 * 256;
        for (int dt = 0; dt < 8; ++dt) {
            __syncthreads();
            stsW<8>(sWT, wr, tid);
            if (dt < 7) ldgW<8>(W, 256, (dt + 1) * 32, wr, tid);
            __syncthreads();
            mma64b(aRow + dt * 32, 256, sWT, acc, colg);
        }
        __syncthreads();
        float bl0[4], bl1[4];
#pragma unroll
        for (int j = 0; j < 4; ++j) { bl0[j] = bias[colg * 4 + j]; bl1[j] = bias[128 + colg * 4 + j]; }
#pragma unroll
        for (int i = 0; i < 8; ++i) {
            const int r = warp * 8 + i;
            const float2 pa = unpk(acc[i][0]), pb = unpk(acc[i][1]);
            const float2 pc = unpk(acc[i][2]), pd = unpk(acc[i][3]);
            *reinterpret_cast<float4*>(sKV + r * 256 + colg * 4) =
                make_float4(pa.x + bl0[0], pa.y + bl0[1], pb.x + bl0[2], pb.y + bl0[3]);
            *reinterpret_cast<float4*>(sKV + r * 256 + 128 + colg * 4) =
                make_float4(pc.x + bl1[0], pc.y + bl1[1], pd.x + bl1[2], pd.y + bl1[3]);
        }
    }
    __syncthreads();

    // ---- Oh = P @ V -> sQ (overwrites Q) ----
    if (tid < 128) {
        const int bl = tid >> 3, h = tid & 7;
        float o[32];
#pragma unroll
        for (int i = 0; i < 32; ++i) o[i] = 0.f;
#pragma unroll
        for (int n = 0; n < 4; ++n) {
            const float p = sP[tid * 4 + n];
            const float* vp = sKV + (bl * 4 + n) * 256 + h * 32;
#pragma unroll
            for (int i = 0; i < 32; ++i) o[i] = fmaf(p, vp[i], o[i]);
        }
        float* op = sQ + bl * 256 + h * 32;
#pragma unroll
        for (int i = 0; i < 32; ++i) op[i] = o[i];
    }

    // ---- Wo: attn_out [16 x 256] -> sAO ----
    {
        const float* W    = Wo + (size_t)m * 65536;
        const float* bias = bo + m * 256;
        Wreg<8> wr;
        ldgW<8>(W, 256, 0, wr, tid);
        u64 acc[2][4];
#pragma unroll
        for (int i = 0; i < 2; ++i)
#pragma unroll
            for (int j = 0; j < 4; ++j) acc[i][j] = 0ULL;
        const float* aRow = sQ + warp * 2 * 256;
        for (int dt = 0; dt < 8; ++dt) {
            __syncthreads();
            stsW<8>(sWT, wr, tid);
            if (dt < 7) ldgW<8>(W, 256, (dt + 1) * 32, wr, tid);
            __syncthreads();
            mma16b(aRow + dt * 32, 256, sWT, acc, colg);
        }
        float bl0[4], bl1[4];
#pragma unroll
        for (int j = 0; j < 4; ++j) { bl0[j] = bias[colg * 4 + j]; bl1[j] = bias[128 + colg * 4 + j]; }
#pragma unroll
        for (int i = 0; i < 2; ++i) {
            const int r = warp * 2 + i;
            const float2 pa = unpk(acc[i][0]), pb = unpk(acc[i][1]);
            const float2 pc = unpk(acc[i][2]), pd = unpk(acc[i][3]);
            *reinterpret_cast<float4*>(sAO + r * 256 + colg * 4) =
                make_float4(pa.x + bl0[0], pa.y + bl0[1], pb.x + bl0[2], pb.y + bl0[3]);
            *reinterpret_cast<float4*>(sAO + r * 256 + 128 + colg * 4) =
                make_float4(pc.x + bl1[0], pc.y + bl1[1], pd.x + bl1[2], pd.y + bl1[3]);
        }
    }

    // ---- gate layer 1: tanh([x_m ; AO] @ g1w^T) [16 x 64] ----
    {
        const float* W = g1w + (size_t)m * 32768;   // [64][512]
        Wreg<2> wr;
        ldgW<2>(W, 512, 0, wr, tid);
        u64 gacc[2] = {0ULL, 0ULL};
        for (int dt = 0; dt < 16; ++dt) {
            __syncthreads();
            stsW<2>(sWT, wr, tid);
            if (dt < 15) ldgW<2>(W, 512, (dt + 1) * 32, wr, tid);
            __syncthreads();
            if (dt < 8)
                mmagb(sX + m * 256 + warp * 2 * 1024 + dt * 32, 1024, sWT, gacc, colg);
            else
                mmagb(sAO + warp * 2 * 256 + (dt - 8) * 32, 256, sWT, gacc, colg);
        }
        const float gb0 = g1b[m * 64 + colg * 2];
        const float gb1 = g1b[m * 64 + colg * 2 + 1];
#pragma unroll
        for (int i = 0; i < 2; ++i) {
            const float2 p = unpk(gacc[i]);
            sGH[(warp * 2 + i) * 64 + colg * 2]     = tanhf(p.x + gb0);
            sGH[(warp * 2 + i) * 64 + colg * 2 + 1] = tanhf(p.y + gb1);
        }
    }
    __syncthreads();

    // ---- gate layer 2 + sigmoid ----
    if (tid < 16) {
        const float* g2 = g2w + m * 64;
        float dot = g2b[m];
#pragma unroll 8
        for (int j = 0; j < 64; ++j) dot = fmaf(sGH[tid * 64 + j], g2[j], dot);
        const float gate = 1.f / (1.f + expf(-dot));
        sGate[tid] = gate;
        out[OUT_GATE_BASE + (size_t)(b0 + tid) * 4 + m] = gate;
    }
    __syncthreads();

    // ---- residual + LayerNorm -> g_y (one warp per batch row, 2 passes) ----
    {
        const int lane = tid & 31;
        for (int bl = warp; bl < 16; bl += 8) {
            const float* xr = sX + (bl * 4 + m) * 256;
            const float gate = sGate[bl];
            float r[8];
            float sum = 0.f;
#pragma unroll
            for (int k = 0; k < 8; ++k) {
                const int d = k * 32 + lane;
                r[k] = xr[d] + gate * sAO[bl * 256 + d];
                sum += r[k];
            }
#pragma unroll
            for (int o = 16; o; o >>= 1) sum += __shfl_xor_sync(0xffffffffu, sum, o);
            const float mu = sum * (1.f / 256.f);
            float var = 0.f;
#pragma unroll
            for (int k = 0; k < 8; ++k) { const float t = r[k] - mu; var = fmaf(t, t, var); }
#pragma unroll
            for (int o = 16; o; o >>= 1) var += __shfl_xor_sync(0xffffffffu, var, o);
            const float rs = rsqrtf(var * (1.f / 256.f) + 1e-5f);
            float* yr = g_y + (size_t)(g0 + bl * 4 + m) * 256;
#pragma unroll
            for (int k = 0; k < 8; ++k) {
                const int d = k * 32 + lane;
                yr[d] = (r[k] - mu) * rs * lng[m * 256 + d] + lnb[m * 256 + d];
            }
        }
    }
}

// =====================================================================
// Kernel 2: FF over y: out = y + f2( gelu(f1(y)) )
// grid (512, 4), 64 batch rows per block, 256 threads, hf chunked by 256
// =====================================================================
#define SM2_Y   0          // [64][256]
#define SM2_HF  16384      // [64][256]
#define SM2_WT  32768      // [32][260]
#define SM2_FLOATS 41088
#define SM2_BYTES  (SM2_FLOATS * 4)

__global__ __launch_bounds__(TPB, 1)
void gcma_part2(const float* __restrict__ f1w, const float* __restrict__ f1b,
                const float* __restrict__ f2w, const float* __restrict__ f2b,
                float* __restrict__ out)
{
    extern __shared__ float sm[];
    float* sY  = sm + SM2_Y;
    float* sHF = sm + SM2_HF;
    float* sWT = sm + SM2_WT;

    const int tid = threadIdx.x;
    const int m   = blockIdx.y;
    const int b0  = blockIdx.x * 64;

    const int warp = tid >> 5;   // 0..7, 8 rows each
    const int colg = tid & 31;   // cols {colg*4..+3, 128+colg*4..+3}

    // load y tile [64 rows][256]
    for (int idx = tid; idx < 4096; idx += TPB) {
        const int r = idx >> 6, q = idx & 63;
        *reinterpret_cast<float4*>(sY + r * 256 + q * 4) =
            *reinterpret_cast<const float4*>(g_y + ((size_t)(b0 + r) * 4 + m) * 256 + q * 4);
    }

    u64 facc[8][4];
#pragma unroll
    for (int i = 0; i < 8; ++i)
#pragma unroll
        for (int j = 0; j < 4; ++j) facc[i][j] = 0ULL;

    const float* aY  = sY  + warp * 8 * 256;
    const float* aHF = sHF + warp * 8 * 256;

    for (int ch = 0; ch < 4; ++ch) {
        // ---- FF1 chunk: hf[:, ch*256 .. +255] ----
        u64 hacc[8][4];
#pragma unroll
        for (int i = 0; i < 8; ++i)
#pragma unroll
            for (int j = 0; j < 4; ++j) hacc[i][j] = 0ULL;
        {
            const float* W1 = f1w + (size_t)m * 262144 + (size_t)ch * 65536;
            Wreg<8> wr;
            ldgW<8>(W1, 256, 0, wr, tid);
            for (int dt = 0; dt < 8; ++dt) {
                __syncthreads();
                stsW<8>(sWT, wr, tid);
                if (dt < 7) ldgW<8>(W1, 256, (dt + 1) * 32, wr, tid);
                __syncthreads();
                mma64b(aY + dt * 32, 256, sWT, hacc, colg);
            }
        }
        __syncthreads();   // previous FF2 reads of sHF complete before overwrite
        // bias + exact GELU -> sHF
        {
            const float* b1 = f1b + m * 1024 + ch * 256;
            float bl0[4], bl1[4];
#pragma unroll
            for (int j = 0; j < 4; ++j) { bl0[j] = b1[colg * 4 + j]; bl1[j] = b1[128 + colg * 4 + j]; }
#pragma unroll
            for (int i = 0; i < 8; ++i) {
                const int r = warp * 8 + i;
                const float2 pa = unpk(hacc[i][0]), pb = unpk(hacc[i][1]);
                const float2 pc = unpk(hacc[i][2]), pd = unpk(hacc[i][3]);
                float v0[4] = {pa.x + bl0[0], pa.y + bl0[1], pb.x + bl0[2], pb.y + bl0[3]};
                float v1[4] = {pc.x + bl1[0], pc.y + bl1[1], pd.x + bl1[2], pd.y + bl1[3]};
#pragma unroll
                for (int j = 0; j < 4; ++j) {
                    v0[j] = 0.5f * v0[j] * (1.f + erff(v0[j] * 0.7071067811865476f));
                    v1[j] = 0.5f * v1[j] * (1.f + erff(v1[j] * 0.7071067811865476f));
                }
                *reinterpret_cast<float4*>(sHF + r * 256 + colg * 4) =
                    make_float4(v0[0], v0[1], v0[2], v0[3]);
                *reinterpret_cast<float4*>(sHF + r * 256 + 128 + colg * 4) =
                    make_float4(v1[0], v1[1], v1[2], v1[3]);
            }
        }
        // ---- FF2 partial ----
        {
            const float* W2 = f2w + (size_t)m * 262144;
            Wreg<8> wr;
            ldgW<8>(W2, 1024, ch * 256, wr, tid);
            for (int dt = 0; dt < 8; ++dt) {
                __syncthreads();
                stsW<8>(sWT, wr, tid);
                if (dt < 7) ldgW<8>(W2, 1024, ch * 256 + (dt + 1) * 32, wr, tid);
                __syncthreads();
                mma64b(aHF + dt * 32, 256, sWT, facc, colg);
            }
        }
    }

    // ---- epilogue: out = y + ff + f2b ----
    {
        const float* b2 = f2b + m * 256;
        float bl0[4], bl1[4];
#pragma unroll
        for (int j = 0; j < 4; ++j) { bl0[j] = b2[colg * 4 + j]; bl1[j] = b2[128 + colg * 4 + j]; }
#pragma unroll
        for (int i = 0; i < 8; ++i) {
            const int r = warp * 8 + i;
            const float4 y0 = *reinterpret_cast<const float4*>(sY + r * 256 + colg * 4);
            const float4 y1 = *reinterpret_cast<const float4*>(sY + r * 256 + 128 + colg * 4);
            const float2 pa = unpk(facc[i][0]), pb = unpk(facc[i][1]);
            const float2 pc = unpk(facc[i][2]), pd = unpk(facc[i][3]);
            float* op = out + ((size_t)(b0 + r) * 4 + m) * 256;
            *reinterpret_cast<float4*>(op + colg * 4) =
                make_float4(y0.x + pa.x + bl0[0], y0.y + pa.y + bl0[1],
                            y0.z + pb.x + bl0[2], y0.w + pb.y + bl0[3]);
            *reinterpret_cast<float4*>(op + 128 + colg * 4) =
                make_float4(y1.x + pc.x + bl1[0], y1.y + pc.y + bl1[1],
                            y1.z + pd.x + bl1[2], y1.w + pd.y + bl1[3]);
        }
    }
}

extern "C" void kernel_launch(void* const* d_in, const int* in_sizes, int n_in,
                              void* d_out, int out_size) {
    const float* x   = (const float*)d_in[0];
    const float* Wq  = (const float*)d_in[1];
    const float* bq  = (const float*)d_in[2];
    const float* Wk  = (const float*)d_in[3];
    const float* bk  = (const float*)d_in[4];
    const float* Wv  = (const float*)d_in[5];
    const float* bv  = (const float*)d_in[6];
    const float* Wo  = (const float*)d_in[7];
    const float* bo  = (const float*)d_in[8];
    const float* g1w = (const float*)d_in[9];
    const float* g1b = (const float*)d_in[10];
    const float* g2w = (const float*)d_in[11];
    const float* g2b = (const float*)d_in[12];
    const float* lng = (const float*)d_in[13];
    const float* lnb = (const float*)d_in[14];
    const float* f1w = (const float*)d_in[15];
    const float* f1b = (const float*)d_in[16];
    const float* f2w = (const float*)d_in[17];
    const float* f2b = (const float*)d_in[18];
    float* out = (float*)d_out;

    cudaFuncSetAttribute(gcma_part1, cudaFuncAttributeMaxDynamicSharedMemorySize, SM1_BYTES);
    cudaFuncSetAttribute(gcma_part2, cudaFuncAttributeMaxDynamicSharedMemorySize, SM2_BYTES);

    dim3 grid1(32768 / 16, 4, 1);
    gcma_part1<<<grid1, TPB, SM1_BYTES>>>(x, Wq, bq, Wk, bk, Wv, bv, Wo, bo,
                                          g1w, g1b, g2w, g2b, lng, lnb, out);
    dim3 grid2(32768 / 64, 4, 1);
    gcma_part2<<<grid2, TPB, SM2_BYTES>>>(f1w, f1b, f2w, f2b, out);
}